// round 2
// baseline (speedup 1.0000x reference)
#include <cuda_runtime.h>
#include <math.h>

// Problem constants
#define BATCH 4
#define SEQ   2048
#define DIM   256
#define HEADS 4
#define DEPTH 64
#define HID   1024
#define MROWS (BATCH*SEQ)      // 8192
#define EPS   1e-3f

// ---------------- scratch (device globals; no allocation allowed) ----------
__device__ float g_wqkv[DIM * 3 * DIM];   // folded BN1 into [256,768] (q|k|v)
__device__ float g_bqkv[3 * DIM];
__device__ float g_w1f[DIM * HID];        // folded BN2 into w1
__device__ float g_b1f[HID];
__device__ float g_qkv[MROWS * 3 * DIM];  // 24 MB
__device__ float g_ctx[MROWS * DIM];      // 8 MB
__device__ float g_x1[MROWS * DIM];       // 8 MB
__device__ float g_m1[MROWS * HID];       // 32 MB

// ---------------- prep: fold batchnorms into weights -----------------------
// bn(x) = a*x + c with a = gamma*rsqrt(var+eps), c = beta - mean*a
// bn(x)@W + b  ==  x @ (diag(a)W) + (c@W + b)
__global__ void prep_kernel(
    const float* __restrict__ g1, const float* __restrict__ b1,
    const float* __restrict__ m1, const float* __restrict__ v1,
    const float* __restrict__ wq, const float* __restrict__ bq,
    const float* __restrict__ wk, const float* __restrict__ bk,
    const float* __restrict__ wv, const float* __restrict__ bv,
    const float* __restrict__ g2, const float* __restrict__ b2,
    const float* __restrict__ m2, const float* __restrict__ v2,
    const float* __restrict__ w1)
{
    int j = blockIdx.x * blockDim.x + threadIdx.x;   // 0..1791
    if (j < 3 * DIM) {
        const float* w; const float* bb; int col;
        if (j < DIM)            { w = wq; bb = bq; col = j; }
        else if (j < 2 * DIM)   { w = wk; bb = bk; col = j - DIM; }
        else                    { w = wv; bb = bv; col = j - 2 * DIM; }
        float bsum = bb[col];
        for (int d = 0; d < DIM; d++) {
            float a = g1[d] * rsqrtf(v1[d] + EPS);
            float c = b1[d] - m1[d] * a;
            float wval = w[d * DIM + col];
            g_wqkv[d * (3 * DIM) + j] = a * wval;
            bsum += c * wval;
        }
        g_bqkv[j] = bsum;
    } else if (j < 3 * DIM + HID) {
        int col = j - 3 * DIM;
        float bsum = 0.f;
        for (int d = 0; d < DIM; d++) {
            float a = g2[d] * rsqrtf(v2[d] + EPS);
            float c = b2[d] - m2[d] * a;
            float wval = w1[d * HID + col];
            g_w1f[d * HID + col] = a * wval;
            bsum += c * wval;
        }
        g_b1f[col] = bsum;
    }
}

// ---------------- generic fp32 GEMM: C = A@B (+bias) (+resid) (gelu) -------
// BM=128, BN=64, BK=16, 256 threads, 8x4 per-thread microtile.
template <bool GELU_>
__global__ void __launch_bounds__(256)
gemm128x64(const float* __restrict__ A, const float* __restrict__ B,
           const float* __restrict__ bias, const float* __restrict__ resid,
           float* __restrict__ C, int M, int N, int K)
{
    __shared__ float As[16][128];
    __shared__ float Bs[16][64];

    const int tid  = threadIdx.x;
    const int row0 = blockIdx.y * 128;
    const int col0 = blockIdx.x * 64;
    const int ty = tid >> 4;       // 0..15
    const int tx = tid & 15;       // 0..15

    float acc[8][4];
#pragma unroll
    for (int i = 0; i < 8; i++)
#pragma unroll
        for (int j = 0; j < 4; j++) acc[i][j] = 0.f;

    for (int k0 = 0; k0 < K; k0 += 16) {
        // A tile: 128x16, stored transposed As[k][m]. 512 float4 loads.
#pragma unroll
        for (int i = 0; i < 2; i++) {
            int idx = tid + i * 256;
            int r   = idx >> 2;            // 0..127
            int c4  = (idx & 3) << 2;      // 0,4,8,12
            float4 v = *(const float4*)(A + (size_t)(row0 + r) * K + k0 + c4);
            As[c4 + 0][r] = v.x;
            As[c4 + 1][r] = v.y;
            As[c4 + 2][r] = v.z;
            As[c4 + 3][r] = v.w;
        }
        // B tile: 16x64 row-major. 256 float4 loads.
        {
            int r  = tid >> 4;
            int c4 = (tid & 15) << 2;
            *(float4*)&Bs[r][c4] =
                *(const float4*)(B + (size_t)(k0 + r) * N + col0 + c4);
        }
        __syncthreads();

#pragma unroll
        for (int k = 0; k < 16; k++) {
            float a[8], bb[4];
            *(float4*)&a[0] = *(float4*)&As[k][ty * 8];
            *(float4*)&a[4] = *(float4*)&As[k][ty * 8 + 4];
            *(float4*)&bb[0] = *(float4*)&Bs[k][tx * 4];
#pragma unroll
            for (int i = 0; i < 8; i++)
#pragma unroll
                for (int j = 0; j < 4; j++)
                    acc[i][j] = fmaf(a[i], bb[j], acc[i][j]);
        }
        __syncthreads();
    }

#pragma unroll
    for (int i = 0; i < 8; i++) {
        int row = row0 + ty * 8 + i;
#pragma unroll
        for (int j = 0; j < 4; j++) {
            int col = col0 + tx * 4 + j;
            float v = acc[i][j];
            if (bias)  v += bias[col];
            if (resid) v += resid[(size_t)row * N + col];
            if (GELU_) v = 0.5f * v * (1.0f + erff(v * 0.70710678118654752f));
            C[(size_t)row * N + col] = v;
        }
    }
}

// ---------------- flash attention ------------------------------------------
// One thread = one query row. Block = 128 query rows of one (b,h).
// grid = (SEQ/128, BATCH*HEADS). K/V tiles of 64 keys in smem; all smem
// reads are warp-uniform (broadcast) float4s.
__global__ void __launch_bounds__(128)
attn_kernel(const float* __restrict__ qkv, float* __restrict__ ctx)
{
    __shared__ float4 Ks[64][16];
    __shared__ float4 Vs[64][16];

    const int tid = threadIdx.x;
    const int bh  = blockIdx.y;
    const int b   = bh >> 2;
    const int h   = bh & 3;
    const int qs  = blockIdx.x * 128 + tid;

    const float* qptr = qkv + (size_t)(b * SEQ + qs) * (3 * DIM) + h * DEPTH;
    float4 q4[16];
#pragma unroll
    for (int c = 0; c < 16; c++) q4[c] = *(const float4*)(qptr + c * 4);

    float4 o4[16];
#pragma unroll
    for (int c = 0; c < 16; c++) o4[c] = make_float4(0.f, 0.f, 0.f, 0.f);
    float m = -1e30f, l = 0.f;

    const float* kvbase = qkv + (size_t)b * SEQ * (3 * DIM) + DIM + h * DEPTH;

    for (int kt = 0; kt < SEQ / 64; kt++) {
        __syncthreads();
#pragma unroll
        for (int i = 0; i < 8; i++) {
            int idx = tid + i * 128;
            int kr  = idx >> 4;
            int c   = idx & 15;
            const float* rp = kvbase + (size_t)(kt * 64 + kr) * (3 * DIM) + c * 4;
            Ks[kr][c] = *(const float4*)rp;
            Vs[kr][c] = *(const float4*)(rp + DIM);   // V is 256 floats after K
        }
        __syncthreads();

        for (int ch = 0; ch < 4; ch++) {
            float s[16];
            float cmax = -1e30f;
#pragma unroll
            for (int jj = 0; jj < 16; jj++) {
                int j = ch * 16 + jj;
                float acc = 0.f;
#pragma unroll
                for (int c = 0; c < 16; c++) {
                    float4 kv = Ks[j][c];
                    acc = fmaf(q4[c].x, kv.x, acc);
                    acc = fmaf(q4[c].y, kv.y, acc);
                    acc = fmaf(q4[c].z, kv.z, acc);
                    acc = fmaf(q4[c].w, kv.w, acc);
                }
                s[jj] = acc * 0.125f;   // 1/sqrt(64)
                cmax  = fmaxf(cmax, s[jj]);
            }
            float mnew  = fmaxf(m, cmax);
            float scale = __expf(m - mnew);
            m = mnew;
            l *= scale;
#pragma unroll
            for (int c = 0; c < 16; c++) {
                o4[c].x *= scale; o4[c].y *= scale;
                o4[c].z *= scale; o4[c].w *= scale;
            }
#pragma unroll
            for (int jj = 0; jj < 16; jj++) {
                float p = __expf(s[jj] - m);
                l += p;
#pragma unroll
                for (int c = 0; c < 16; c++) {
                    float4 vv = Vs[ch * 16 + jj][c];
                    o4[c].x = fmaf(p, vv.x, o4[c].x);
                    o4[c].y = fmaf(p, vv.y, o4[c].y);
                    o4[c].z = fmaf(p, vv.z, o4[c].z);
                    o4[c].w = fmaf(p, vv.w, o4[c].w);
                }
            }
        }
    }

    float inv = 1.f / l;
    float* op = ctx + (size_t)(b * SEQ + qs) * DIM + h * DEPTH;
#pragma unroll
    for (int c = 0; c < 16; c++) {
        float4 v = o4[c];
        v.x *= inv; v.y *= inv; v.z *= inv; v.w *= inv;
        *(float4*)(op + c * 4) = v;
    }
}

// ---------------- launch ----------------------------------------------------
extern "C" void kernel_launch(void* const* d_in, const int* in_sizes, int n_in,
                              void* d_out, int out_size)
{
    const float* x    = (const float*)d_in[0];
    const float* b1g  = (const float*)d_in[1];
    const float* b1b  = (const float*)d_in[2];
    const float* b1m  = (const float*)d_in[3];
    const float* b1v  = (const float*)d_in[4];
    const float* wq   = (const float*)d_in[5];
    const float* bq   = (const float*)d_in[6];
    const float* wk   = (const float*)d_in[7];
    const float* bk   = (const float*)d_in[8];
    const float* wv   = (const float*)d_in[9];
    const float* bv   = (const float*)d_in[10];
    const float* wo   = (const float*)d_in[11];
    const float* bo   = (const float*)d_in[12];
    const float* b2g  = (const float*)d_in[13];
    const float* b2b  = (const float*)d_in[14];
    const float* b2m  = (const float*)d_in[15];
    const float* b2v  = (const float*)d_in[16];
    const float* w1   = (const float*)d_in[17];
    const float* w2   = (const float*)d_in[18];
    float* out = (float*)d_out;

    float *p_wqkv, *p_bqkv, *p_w1f, *p_b1f, *p_qkv, *p_ctx, *p_x1, *p_m1;
    cudaGetSymbolAddress((void**)&p_wqkv, g_wqkv);
    cudaGetSymbolAddress((void**)&p_bqkv, g_bqkv);
    cudaGetSymbolAddress((void**)&p_w1f,  g_w1f);
    cudaGetSymbolAddress((void**)&p_b1f,  g_b1f);
    cudaGetSymbolAddress((void**)&p_qkv,  g_qkv);
    cudaGetSymbolAddress((void**)&p_ctx,  g_ctx);
    cudaGetSymbolAddress((void**)&p_x1,   g_x1);
    cudaGetSymbolAddress((void**)&p_m1,   g_m1);

    // 1. fold BN1 into wq/wk/wv, BN2 into w1
    prep_kernel<<<7, 256>>>(b1g, b1b, b1m, b1v, wq, bq, wk, bk, wv, bv,
                            b2g, b2b, b2m, b2v, w1);

    // 2. fused QKV projection: g_qkv[8192,768] = x @ g_wqkv + g_bqkv
    gemm128x64<false><<<dim3(3 * DIM / 64, MROWS / 128), 256>>>(
        x, p_wqkv, p_bqkv, nullptr, p_qkv, MROWS, 3 * DIM, DIM);

    // 3. flash attention -> g_ctx[8192,256]
    attn_kernel<<<dim3(SEQ / 128, BATCH * HEADS), 128>>>(p_qkv, p_ctx);

    // 4. out projection + residual: g_x1 = ctx @ wo + bo + x
    gemm128x64<false><<<dim3(DIM / 64, MROWS / 128), 256>>>(
        p_ctx, wo, bo, x, p_x1, MROWS, DIM, DIM);

    // 5. FFN1 (+folded BN2) + GELU: g_m1 = gelu(x1 @ w1f + b1f)
    gemm128x64<true><<<dim3(HID / 64, MROWS / 128), 256>>>(
        p_x1, p_w1f, p_b1f, nullptr, p_m1, MROWS, HID, DIM);

    // 6. FFN2 + residual: out = m1 @ w2 + x1
    gemm128x64<false><<<dim3(DIM / 64, MROWS / 128), 256>>>(
        p_m1, w2, nullptr, p_x1, out, MROWS, DIM, HID);
}

// round 4
// speedup vs baseline: 1.0765x; 1.0765x over previous
#include <cuda_runtime.h>
#include <cuda_bf16.h>
#include <math.h>
#include <stdint.h>

// Problem constants
#define BATCH 4
#define SEQ   2048
#define DIM   256
#define HEADS 4
#define DEPTH 64
#define HID   1024
#define MROWS (BATCH*SEQ)      // 8192
#define EPS   1e-3f

typedef unsigned long long u64t;

// ===================== PTX helpers ==========================================
__device__ __forceinline__ uint32_t smem_u32(const void* p) {
    uint32_t a;
    asm("{ .reg .u64 t; cvta.to.shared.u64 t, %1; cvt.u32.u64 %0, t; }"
        : "=r"(a) : "l"(p));
    return a;
}

__device__ __forceinline__ void ldsm4(uint32_t addr, uint32_t* r) {
    asm volatile("ldmatrix.sync.aligned.m8n8.x4.shared.b16 {%0,%1,%2,%3}, [%4];"
                 : "=r"(r[0]), "=r"(r[1]), "=r"(r[2]), "=r"(r[3]) : "r"(addr));
}
__device__ __forceinline__ void ldsm2(uint32_t addr, uint32_t* r) {
    asm volatile("ldmatrix.sync.aligned.m8n8.x2.shared.b16 {%0,%1}, [%2];"
                 : "=r"(r[0]), "=r"(r[1]) : "r"(addr));
}
__device__ __forceinline__ void mma16816(float* c, const uint32_t* a, const uint32_t* b) {
    asm volatile(
        "mma.sync.aligned.m16n8k16.row.col.f32.bf16.bf16.f32 "
        "{%0,%1,%2,%3}, {%4,%5,%6,%7}, {%8,%9}, {%0,%1,%2,%3};"
        : "+f"(c[0]), "+f"(c[1]), "+f"(c[2]), "+f"(c[3])
        : "r"(a[0]), "r"(a[1]), "r"(a[2]), "r"(a[3]), "r"(b[0]), "r"(b[1]));
}

// packed fp32x2
__device__ __forceinline__ u64t fma2(u64t a, u64t b, u64t c) {
    u64t d; asm("fma.rn.f32x2 %0, %1, %2, %3;" : "=l"(d) : "l"(a), "l"(b), "l"(c)); return d;
}
__device__ __forceinline__ u64t mul2(u64t a, u64t b) {
    u64t d; asm("mul.rn.f32x2 %0, %1, %2;" : "=l"(d) : "l"(a), "l"(b)); return d;
}
__device__ __forceinline__ u64t pack2(float x, float y) {
    u64t d; asm("mov.b64 %0, {%1, %2};" : "=l"(d) : "f"(x), "f"(y)); return d;
}
#define UNPACK2(lo_, hi_, v) asm("mov.b64 {%0,%1}, %2;" : "=f"(lo_), "=f"(hi_) : "l"(v))

// ===================== scratch (device globals) =============================
__device__ float g_bqkv[3 * DIM];
__device__ float g_b1f[HID];
__device__ __align__(16) __nv_bfloat16 g_qkvT_hi[3 * DIM * DIM], g_qkvT_lo[3 * DIM * DIM];
__device__ __align__(16) __nv_bfloat16 g_woT_hi[DIM * DIM],      g_woT_lo[DIM * DIM];
__device__ __align__(16) __nv_bfloat16 g_w1T_hi[HID * DIM],      g_w1T_lo[HID * DIM];
__device__ __align__(16) __nv_bfloat16 g_w2T_hi[DIM * HID],      g_w2T_lo[DIM * HID];
__device__ float g_qkv[MROWS * 3 * DIM];
__device__ float g_ctx[MROWS * DIM];
__device__ float g_x1[MROWS * DIM];
__device__ float g_m1[MROWS * HID];

__device__ __forceinline__ void split_bf16(float x, __nv_bfloat16& h, __nv_bfloat16& l) {
    h = __float2bfloat16_rn(x);
    l = __float2bfloat16_rn(x - __bfloat162float(h));
}

// ===================== prep: fold BN, transpose, split ======================
__global__ void prep_kernel(
    const float* __restrict__ g1, const float* __restrict__ b1,
    const float* __restrict__ m1, const float* __restrict__ v1,
    const float* __restrict__ wq, const float* __restrict__ bq,
    const float* __restrict__ wk, const float* __restrict__ bk,
    const float* __restrict__ wv, const float* __restrict__ bv,
    const float* __restrict__ g2, const float* __restrict__ b2,
    const float* __restrict__ m2, const float* __restrict__ v2,
    const float* __restrict__ w1, const float* __restrict__ wo,
    const float* __restrict__ w2)
{
    int j = blockIdx.x * blockDim.x + threadIdx.x;
    if (j < 3 * DIM) {                       // QKV fold + transpose + split
        const float* w; const float* bb; int col;
        if (j < DIM)          { w = wq; bb = bq; col = j; }
        else if (j < 2 * DIM) { w = wk; bb = bk; col = j - DIM; }
        else                  { w = wv; bb = bv; col = j - 2 * DIM; }
        float bsum = bb[col];
        for (int d = 0; d < DIM; d++) {
            float a = g1[d] * rsqrtf(v1[d] + EPS);
            float c = b1[d] - m1[d] * a;
            float wv_ = a * w[d * DIM + col];
            __nv_bfloat16 h, l; split_bf16(wv_, h, l);
            g_qkvT_hi[j * DIM + d] = h; g_qkvT_lo[j * DIM + d] = l;
            bsum += c * w[d * DIM + col];
        }
        g_bqkv[j] = bsum;
    } else if (j < 3 * DIM + HID) {          // W1 fold (BN2) + transpose + split
        int col = j - 3 * DIM;
        float bsum = 0.f;
        for (int d = 0; d < DIM; d++) {
            float a = g2[d] * rsqrtf(v2[d] + EPS);
            float c = b2[d] - m2[d] * a;
            float wv_ = a * w1[d * HID + col];
            __nv_bfloat16 h, l; split_bf16(wv_, h, l);
            g_w1T_hi[col * DIM + d] = h; g_w1T_lo[col * DIM + d] = l;
            bsum += c * w1[d * HID + col];
        }
        g_b1f[col] = bsum;
    } else if (j < 3 * DIM + HID + DIM) {    // Wo transpose + split
        int n = j - (3 * DIM + HID);
        for (int k = 0; k < DIM; k++) {
            __nv_bfloat16 h, l; split_bf16(wo[k * DIM + n], h, l);
            g_woT_hi[n * DIM + k] = h; g_woT_lo[n * DIM + k] = l;
        }
    } else if (j < 3 * DIM + HID + 2 * DIM) { // W2 transpose + split
        int n = j - (3 * DIM + HID + DIM);
        for (int k = 0; k < HID; k++) {
            __nv_bfloat16 h, l; split_bf16(w2[k * DIM + n], h, l);
            g_w2T_hi[n * HID + k] = h; g_w2T_lo[n * HID + k] = l;
        }
    }
}

// ===================== mma.sync split-bf16 GEMM =============================
// C[M,N] = A[M,K] @ B[K,N], B given transposed+split (Bth/Btl [N,K] bf16).
// CTA tile 128x128, 8 warps (2M x 4N), warp tile 64x32, K-chunk 32.
// 3-term: AhBh + AhBl + AlBh, fp32 accumulate.
#define ASTRIDE 40                       // bf16 per smem row (32 data + 8 pad)
#define TILE_B  (128 * ASTRIDE * 2)      // 10240 bytes per tile array
#define BUF_B   (4 * TILE_B)             // Ah Al Bh Bl
#define GSMEM_B (2 * BUF_B)              // double buffer: 81920

__global__ void __launch_bounds__(256)
gemm_mma(const float* __restrict__ A,
         const __nv_bfloat16* __restrict__ Bth, const __nv_bfloat16* __restrict__ Btl,
         const float* __restrict__ bias, const float* __restrict__ resid,
         float* __restrict__ C, int M, int N, int K, int gelu)
{
    extern __shared__ __align__(16) char smem[];
    const int tid  = threadIdx.x;
    const int wid  = tid >> 5;
    const int lane = tid & 31;
    const int m0 = blockIdx.y * 128;
    const int n0 = blockIdx.x * 128;
    const int warpM = (wid & 1) * 64;
    const int warpN = (wid >> 1) * 32;

    // loader indices: each thread owns row (tid>>1), 16 k-elems at (tid&1)*16
    const int lrow = tid >> 1;
    const int lko  = (tid & 1) * 16;

    // ldmatrix address components
    const int aRowOff = (lane & 7) + ((lane >> 3) & 1) * 8;  // within 16-row tile
    const int aKpart  = ((lane >> 4) & 1) * 8;
    const int bl2     = lane & 15;
    const int bRowOff = bl2 & 7;
    const int bKpart  = (bl2 >> 3) * 8;

    const uint32_t sbase = smem_u32(smem);

    float acc[4][4][4];
#pragma unroll
    for (int i = 0; i < 4; i++)
#pragma unroll
        for (int j = 0; j < 4; j++)
#pragma unroll
            for (int e = 0; e < 4; e++) acc[i][j][e] = 0.f;

    const int nch = K >> 5;
    float4 aR[4];
    uint4  bhR[2], blR[2];

    // ---- preload chunk 0 ----
    {
        const float* ap = A + (size_t)(m0 + lrow) * K + lko;
#pragma unroll
        for (int i = 0; i < 4; i++) aR[i] = ((const float4*)ap)[i];
        const __nv_bfloat16* bp = Bth + (size_t)(n0 + lrow) * K + lko;
        const __nv_bfloat16* lp = Btl + (size_t)(n0 + lrow) * K + lko;
        bhR[0] = ((const uint4*)bp)[0]; bhR[1] = ((const uint4*)bp)[1];
        blR[0] = ((const uint4*)lp)[0]; blR[1] = ((const uint4*)lp)[1];
    }

    for (int c = 0; c < nch; c++) {
        const int buf = c & 1;
        char* base = smem + buf * BUF_B;
        __syncthreads();
        // ---- store staged regs (split A to hi/lo bf16) ----
        {
            const int rb = lrow * (ASTRIDE * 2) + lko * 2;   // byte offset
#pragma unroll
            for (int i = 0; i < 2; i++) {
                float4 f0 = aR[i * 2], f1 = aR[i * 2 + 1];
                __nv_bfloat162 h01 = __floats2bfloat162_rn(f0.x, f0.y);
                __nv_bfloat162 h23 = __floats2bfloat162_rn(f0.z, f0.w);
                __nv_bfloat162 h45 = __floats2bfloat162_rn(f1.x, f1.y);
                __nv_bfloat162 h67 = __floats2bfloat162_rn(f1.z, f1.w);
                __nv_bfloat162 l01 = __floats2bfloat162_rn(f0.x - __bfloat162float(h01.x),
                                                           f0.y - __bfloat162float(h01.y));
                __nv_bfloat162 l23 = __floats2bfloat162_rn(f0.z - __bfloat162float(h23.x),
                                                           f0.w - __bfloat162float(h23.y));
                __nv_bfloat162 l45 = __floats2bfloat162_rn(f1.x - __bfloat162float(h45.x),
                                                           f1.y - __bfloat162float(h45.y));
                __nv_bfloat162 l67 = __floats2bfloat162_rn(f1.z - __bfloat162float(h67.x),
                                                           f1.w - __bfloat162float(h67.y));
                uint4 hv = { *(uint32_t*)&h01, *(uint32_t*)&h23,
                             *(uint32_t*)&h45, *(uint32_t*)&h67 };
                uint4 lv = { *(uint32_t*)&l01, *(uint32_t*)&l23,
                             *(uint32_t*)&l45, *(uint32_t*)&l67 };
                *(uint4*)(base + rb + i * 16)              = hv;
                *(uint4*)(base + TILE_B + rb + i * 16)     = lv;
            }
            *(uint4*)(base + 2 * TILE_B + rb)      = bhR[0];
            *(uint4*)(base + 2 * TILE_B + rb + 16) = bhR[1];
            *(uint4*)(base + 3 * TILE_B + rb)      = blR[0];
            *(uint4*)(base + 3 * TILE_B + rb + 16) = blR[1];
        }
        __syncthreads();

        // ---- prefetch next chunk into regs ----
        if (c + 1 < nch) {
            const int k0 = (c + 1) << 5;
            const float* ap = A + (size_t)(m0 + lrow) * K + k0 + lko;
#pragma unroll
            for (int i = 0; i < 4; i++) aR[i] = ((const float4*)ap)[i];
            const __nv_bfloat16* bp = Bth + (size_t)(n0 + lrow) * K + k0 + lko;
            const __nv_bfloat16* lp = Btl + (size_t)(n0 + lrow) * K + k0 + lko;
            bhR[0] = ((const uint4*)bp)[0]; bhR[1] = ((const uint4*)bp)[1];
            blR[0] = ((const uint4*)lp)[0]; blR[1] = ((const uint4*)lp)[1];
        }

        // ---- compute on buf ----
        const uint32_t Ah = sbase + buf * BUF_B;
        const uint32_t Al = Ah + TILE_B;
        const uint32_t Bh = Ah + 2 * TILE_B;
        const uint32_t Bl = Ah + 3 * TILE_B;
#pragma unroll
        for (int ks = 0; ks < 2; ks++) {
            uint32_t ah[4][4], al[4][4], bh[4][2], blf[4][2];
#pragma unroll
            for (int mi = 0; mi < 4; mi++) {
                uint32_t off = ((warpM + mi * 16 + aRowOff) * ASTRIDE
                                + ks * 16 + aKpart) * 2;
                ldsm4(Ah + off, ah[mi]);
                ldsm4(Al + off, al[mi]);
            }
#pragma unroll
            for (int nj = 0; nj < 4; nj++) {
                uint32_t off = ((warpN + nj * 8 + bRowOff) * ASTRIDE
                                + ks * 16 + bKpart) * 2;
                ldsm2(Bh + off, bh[nj]);
                ldsm2(Bl + off, blf[nj]);
            }
#pragma unroll
            for (int mi = 0; mi < 4; mi++)
#pragma unroll
                for (int nj = 0; nj < 4; nj++) {
                    mma16816(acc[mi][nj], ah[mi], bh[nj]);
                    mma16816(acc[mi][nj], ah[mi], blf[nj]);
                    mma16816(acc[mi][nj], al[mi], bh[nj]);
                }
        }
    }

    // ---- epilogue ----
    const int g   = lane >> 2;
    const int tig = lane & 3;
#pragma unroll
    for (int mi = 0; mi < 4; mi++) {
#pragma unroll
        for (int half = 0; half < 2; half++) {
            int row = m0 + warpM + mi * 16 + g + half * 8;
#pragma unroll
            for (int nj = 0; nj < 4; nj++) {
                int col = n0 + warpN + nj * 8 + tig * 2;
                float vx = acc[mi][nj][half * 2 + 0];
                float vy = acc[mi][nj][half * 2 + 1];
                if (bias)  { vx += bias[col]; vy += bias[col + 1]; }
                if (resid) {
                    const float* rp = resid + (size_t)row * N + col;
                    vx += rp[0]; vy += rp[1];
                }
                if (gelu) {
                    vx = 0.5f * vx * (1.0f + erff(vx * 0.70710678118654752f));
                    vy = 0.5f * vy * (1.0f + erff(vy * 0.70710678118654752f));
                }
                *(float2*)(C + (size_t)row * N + col) = make_float2(vx, vy);
            }
        }
    }
}

// ===================== flash attention (packed f32x2) =======================
__global__ void __launch_bounds__(128)
attn_kernel(const float* __restrict__ qkv, float* __restrict__ ctx)
{
    __shared__ ulonglong2 Ks[64][16];
    __shared__ ulonglong2 Vs[64][16];

    const int tid = threadIdx.x;
    const int bh  = blockIdx.y;
    const int b   = bh >> 2;
    const int h   = bh & 3;
    const int qs  = blockIdx.x * 128 + tid;

    const ulonglong2* qp =
        (const ulonglong2*)(qkv + (size_t)(b * SEQ + qs) * (3 * DIM) + h * DEPTH);
    ulonglong2 q2[16];
#pragma unroll
    for (int c = 0; c < 16; c++) q2[c] = qp[c];

    u64t oa[16], ob[16];
#pragma unroll
    for (int c = 0; c < 16; c++) { oa[c] = 0ull; ob[c] = 0ull; }
    float m = -1e30f, l = 0.f;

    const float* kvb = qkv + (size_t)b * SEQ * (3 * DIM) + DIM + h * DEPTH;

    for (int kt = 0; kt < SEQ / 64; kt++) {
        __syncthreads();
#pragma unroll
        for (int i = 0; i < 8; i++) {
            int idx = tid + i * 128;
            int kr  = idx >> 4;
            int c   = idx & 15;
            const float* rp = kvb + (size_t)(kt * 64 + kr) * (3 * DIM);
            Ks[kr][c] = *(const ulonglong2*)(rp + c * 4);
            Vs[kr][c] = *(const ulonglong2*)(rp + DIM + c * 4);
        }
        __syncthreads();

        for (int ch = 0; ch < 4; ch++) {
            float s[16];
            float cmax = -1e30f;
#pragma unroll
            for (int jj = 0; jj < 16; jj++) {
                int j = ch * 16 + jj;
                u64t a0 = 0ull, a1 = 0ull;
#pragma unroll
                for (int c = 0; c < 16; c++) {
                    ulonglong2 kv = Ks[j][c];
                    a0 = fma2(q2[c].x, kv.x, a0);
                    a1 = fma2(q2[c].y, kv.y, a1);
                }
                float x0, x1, y0, y1;
                UNPACK2(x0, x1, a0);
                UNPACK2(y0, y1, a1);
                s[jj] = ((x0 + y0) + (x1 + y1)) * 0.125f;
                cmax  = fmaxf(cmax, s[jj]);
            }
            float mnew  = fmaxf(m, cmax);
            float scale = __expf(m - mnew);
            m = mnew;
            l *= scale;
            u64t s2 = pack2(scale, scale);
#pragma unroll
            for (int c = 0; c < 16; c++) { oa[c] = mul2(oa[c], s2); ob[c] = mul2(ob[c], s2); }
#pragma unroll
            for (int jj = 0; jj < 16; jj++) {
                float p = __expf(s[jj] - m);
                l += p;
                u64t p2 = pack2(p, p);
#pragma unroll
                for (int c = 0; c < 16; c++) {
                    ulonglong2 vv = Vs[ch * 16 + jj][c];
                    oa[c] = fma2(p2, vv.x, oa[c]);
                    ob[c] = fma2(p2, vv.y, ob[c]);
                }
            }
        }
    }

    float inv = 1.f / l;
    float* op = ctx + (size_t)(b * SEQ + qs) * DIM + h * DEPTH;
#pragma unroll
    for (int c = 0; c < 16; c++) {
        float4 v;
        UNPACK2(v.x, v.y, oa[c]);
        UNPACK2(v.z, v.w, ob[c]);
        v.x *= inv; v.y *= inv; v.z *= inv; v.w *= inv;
        *(float4*)(op + c * 4) = v;
    }
}

// ===================== launch ===============================================
extern "C" void kernel_launch(void* const* d_in, const int* in_sizes, int n_in,
                              void* d_out, int out_size)
{
    const float* x    = (const float*)d_in[0];
    const float* b1g  = (const float*)d_in[1];
    const float* b1b  = (const float*)d_in[2];
    const float* b1m  = (const float*)d_in[3];
    const float* b1v  = (const float*)d_in[4];
    const float* wq   = (const float*)d_in[5];
    const float* bq   = (const float*)d_in[6];
    const float* wk   = (const float*)d_in[7];
    const float* bk   = (const float*)d_in[8];
    const float* wv   = (const float*)d_in[9];
    const float* bv   = (const float*)d_in[10];
    const float* wo   = (const float*)d_in[11];
    const float* bo   = (const float*)d_in[12];
    const float* b2g  = (const float*)d_in[13];
    const float* b2b  = (const float*)d_in[14];
    const float* b2m  = (const float*)d_in[15];
    const float* b2v  = (const float*)d_in[16];
    const float* w1   = (const float*)d_in[17];
    const float* w2   = (const float*)d_in[18];
    float* out = (float*)d_out;

    float *p_bqkv, *p_b1f, *p_qkv, *p_ctx, *p_x1, *p_m1;
    __nv_bfloat16 *p_qkvTh, *p_qkvTl, *p_woTh, *p_woTl, *p_w1Th, *p_w1Tl, *p_w2Th, *p_w2Tl;
    cudaGetSymbolAddress((void**)&p_bqkv,  g_bqkv);
    cudaGetSymbolAddress((void**)&p_b1f,   g_b1f);
    cudaGetSymbolAddress((void**)&p_qkv,   g_qkv);
    cudaGetSymbolAddress((void**)&p_ctx,   g_ctx);
    cudaGetSymbolAddress((void**)&p_x1,    g_x1);
    cudaGetSymbolAddress((void**)&p_m1,    g_m1);
    cudaGetSymbolAddress((void**)&p_qkvTh, g_qkvT_hi);
    cudaGetSymbolAddress((void**)&p_qkvTl, g_qkvT_lo);
    cudaGetSymbolAddress((void**)&p_woTh,  g_woT_hi);
    cudaGetSymbolAddress((void**)&p_woTl,  g_woT_lo);
    cudaGetSymbolAddress((void**)&p_w1Th,  g_w1T_hi);
    cudaGetSymbolAddress((void**)&p_w1Tl,  g_w1T_lo);
    cudaGetSymbolAddress((void**)&p_w2Th,  g_w2T_hi);
    cudaGetSymbolAddress((void**)&p_w2Tl,  g_w2T_lo);

    cudaFuncSetAttribute(gemm_mma, cudaFuncAttributeMaxDynamicSharedMemorySize, GSMEM_B);

    // 1. fold BN, transpose, split weights
    prep_kernel<<<9, 256>>>(b1g, b1b, b1m, b1v, wq, bq, wk, bk, wv, bv,
                            b2g, b2b, b2m, b2v, w1, wo, w2);

    // 2. QKV projection (BN1 folded): g_qkv = x @ wqkv + bqkv   [8192 x 768]
    gemm_mma<<<dim3(6, 64), 256, GSMEM_B>>>(
        x, p_qkvTh, p_qkvTl, p_bqkv, nullptr, p_qkv, MROWS, 3 * DIM, DIM, 0);

    // 3. flash attention -> g_ctx
    attn_kernel<<<dim3(SEQ / 128, BATCH * HEADS), 128>>>(p_qkv, p_ctx);

    // 4. out projection + residual: g_x1 = ctx @ wo + bo + x
    gemm_mma<<<dim3(2, 64), 256, GSMEM_B>>>(
        p_ctx, p_woTh, p_woTl, bo, x, p_x1, MROWS, DIM, DIM, 0);

    // 5. FFN1 (BN2 folded) + GELU: g_m1 = gelu(x1 @ w1f + b1f)
    gemm_mma<<<dim3(8, 64), 256, GSMEM_B>>>(
        p_x1, p_w1Th, p_w1Tl, p_b1f, nullptr, p_m1, MROWS, HID, DIM, 1);

    // 6. FFN2 + residual: out = m1 @ w2 + x1
    gemm_mma<<<dim3(2, 64), 256, GSMEM_B>>>(
        p_m1, p_w2Th, p_w2Tl, nullptr, p_x1, out, MROWS, DIM, HID, 0);
}

// round 5
// speedup vs baseline: 2.0894x; 1.9408x over previous
#include <cuda_runtime.h>
#include <cuda_bf16.h>
#include <math.h>
#include <stdint.h>

// Problem constants
#define BATCH 4
#define SEQ   2048
#define DIM   256
#define HEADS 4
#define DEPTH 64
#define HID   1024
#define MROWS (BATCH*SEQ)      // 8192
#define EPS   1e-3f

// ===================== PTX helpers ==========================================
__device__ __forceinline__ uint32_t smem_u32(const void* p) {
    uint32_t a;
    asm("{ .reg .u64 t; cvta.to.shared.u64 t, %1; cvt.u32.u64 %0, t; }"
        : "=r"(a) : "l"(p));
    return a;
}
__device__ __forceinline__ void ldsm4(uint32_t addr, uint32_t* r) {
    asm volatile("ldmatrix.sync.aligned.m8n8.x4.shared.b16 {%0,%1,%2,%3}, [%4];"
                 : "=r"(r[0]), "=r"(r[1]), "=r"(r[2]), "=r"(r[3]) : "r"(addr));
}
__device__ __forceinline__ void ldsm4t(uint32_t addr, uint32_t* r) {
    asm volatile("ldmatrix.sync.aligned.m8n8.x4.trans.shared.b16 {%0,%1,%2,%3}, [%4];"
                 : "=r"(r[0]), "=r"(r[1]), "=r"(r[2]), "=r"(r[3]) : "r"(addr));
}
__device__ __forceinline__ void ldsm2(uint32_t addr, uint32_t* r) {
    asm volatile("ldmatrix.sync.aligned.m8n8.x2.shared.b16 {%0,%1}, [%2];"
                 : "=r"(r[0]), "=r"(r[1]) : "r"(addr));
}
__device__ __forceinline__ void mma16816(float* c, const uint32_t* a, const uint32_t* b) {
    asm volatile(
        "mma.sync.aligned.m16n8k16.row.col.f32.bf16.bf16.f32 "
        "{%0,%1,%2,%3}, {%4,%5,%6,%7}, {%8,%9}, {%0,%1,%2,%3};"
        : "+f"(c[0]), "+f"(c[1]), "+f"(c[2]), "+f"(c[3])
        : "r"(a[0]), "r"(a[1]), "r"(a[2]), "r"(a[3]), "r"(b[0]), "r"(b[1]));
}

// ===================== scratch (device globals) =============================
#define ATT_R ((size_t)16 * SEQ * DEPTH)   // one region: [BH=16][S][64]
__device__ float g_bqkv[3 * DIM];
__device__ float g_b1f[HID];
__device__ __align__(16) __nv_bfloat16 g_qkvT_hi[3 * DIM * DIM], g_qkvT_lo[3 * DIM * DIM];
__device__ __align__(16) __nv_bfloat16 g_woT_hi[DIM * DIM],      g_woT_lo[DIM * DIM];
__device__ __align__(16) __nv_bfloat16 g_w1T_hi[HID * DIM],      g_w1T_lo[HID * DIM];
__device__ __align__(16) __nv_bfloat16 g_w2T_hi[DIM * HID],      g_w2T_lo[DIM * HID];
__device__ __align__(16) __nv_bfloat16 g_att[6 * 16 * SEQ * DEPTH];  // qh,ql,kh,kl,vh,vl
__device__ float g_ctx[MROWS * DIM];
__device__ float g_x1[MROWS * DIM];
__device__ float g_m1[MROWS * HID];

__device__ __forceinline__ void split_bf16(float x, __nv_bfloat16& h, __nv_bfloat16& l) {
    h = __float2bfloat16_rn(x);
    l = __float2bfloat16_rn(x - __bfloat162float(h));
}

// ===================== prep: fold BN, transpose, split ======================
__global__ void prep_kernel(
    const float* __restrict__ g1, const float* __restrict__ b1,
    const float* __restrict__ m1, const float* __restrict__ v1,
    const float* __restrict__ wq, const float* __restrict__ bq,
    const float* __restrict__ wk, const float* __restrict__ bk,
    const float* __restrict__ wv, const float* __restrict__ bv,
    const float* __restrict__ g2, const float* __restrict__ b2,
    const float* __restrict__ m2, const float* __restrict__ v2,
    const float* __restrict__ w1, const float* __restrict__ wo,
    const float* __restrict__ w2)
{
    int j = blockIdx.x * blockDim.x + threadIdx.x;
    if (j < 3 * DIM) {
        const float* w; const float* bb; int col;
        if (j < DIM)          { w = wq; bb = bq; col = j; }
        else if (j < 2 * DIM) { w = wk; bb = bk; col = j - DIM; }
        else                  { w = wv; bb = bv; col = j - 2 * DIM; }
        float bsum = bb[col];
        for (int d = 0; d < DIM; d++) {
            float a = g1[d] * rsqrtf(v1[d] + EPS);
            float c = b1[d] - m1[d] * a;
            float wv_ = a * w[d * DIM + col];
            __nv_bfloat16 h, l; split_bf16(wv_, h, l);
            g_qkvT_hi[j * DIM + d] = h; g_qkvT_lo[j * DIM + d] = l;
            bsum += c * w[d * DIM + col];
        }
        g_bqkv[j] = bsum;
    } else if (j < 3 * DIM + HID) {
        int col = j - 3 * DIM;
        float bsum = 0.f;
        for (int d = 0; d < DIM; d++) {
            float a = g2[d] * rsqrtf(v2[d] + EPS);
            float c = b2[d] - m2[d] * a;
            float wv_ = a * w1[d * HID + col];
            __nv_bfloat16 h, l; split_bf16(wv_, h, l);
            g_w1T_hi[col * DIM + d] = h; g_w1T_lo[col * DIM + d] = l;
            bsum += c * w1[d * HID + col];
        }
        g_b1f[col] = bsum;
    } else if (j < 3 * DIM + HID + DIM) {
        int n = j - (3 * DIM + HID);
        for (int k = 0; k < DIM; k++) {
            __nv_bfloat16 h, l; split_bf16(wo[k * DIM + n], h, l);
            g_woT_hi[n * DIM + k] = h; g_woT_lo[n * DIM + k] = l;
        }
    } else if (j < 3 * DIM + HID + 2 * DIM) {
        int n = j - (3 * DIM + HID + DIM);
        for (int k = 0; k < HID; k++) {
            __nv_bfloat16 h, l; split_bf16(w2[k * DIM + n], h, l);
            g_w2T_hi[n * HID + k] = h; g_w2T_lo[n * HID + k] = l;
        }
    }
}

// ===================== mma.sync split-bf16 GEMM =============================
// mode 0: C = A@B + bias (+resid). mode 1: + GELU. mode 2: qkv-split output
// into g_att regions (no C write).
#define ASTRIDE 40
#define TILE_B  (128 * ASTRIDE * 2)
#define BUF_B   (4 * TILE_B)
#define GSMEM_B (2 * BUF_B)

__global__ void __launch_bounds__(256)
gemm_mma(const float* __restrict__ A,
         const __nv_bfloat16* __restrict__ Bth, const __nv_bfloat16* __restrict__ Btl,
         const float* __restrict__ bias, const float* __restrict__ resid,
         float* __restrict__ C, __nv_bfloat16* __restrict__ att,
         int M, int N, int K, int mode)
{
    extern __shared__ __align__(16) char smem[];
    const int tid  = threadIdx.x;
    const int wid  = tid >> 5;
    const int lane = tid & 31;
    const int m0 = blockIdx.y * 128;
    const int n0 = blockIdx.x * 128;
    const int warpM = (wid & 1) * 64;
    const int warpN = (wid >> 1) * 32;

    const int lrow = tid >> 1;
    const int lko  = (tid & 1) * 16;

    const int aRowOff = (lane & 7) + ((lane >> 3) & 1) * 8;
    const int aKpart  = ((lane >> 4) & 1) * 8;
    const int bl2     = lane & 15;
    const int bRowOff = bl2 & 7;
    const int bKpart  = (bl2 >> 3) * 8;

    const uint32_t sbase = smem_u32(smem);

    float acc[4][4][4];
#pragma unroll
    for (int i = 0; i < 4; i++)
#pragma unroll
        for (int j = 0; j < 4; j++)
#pragma unroll
            for (int e = 0; e < 4; e++) acc[i][j][e] = 0.f;

    const int nch = K >> 5;
    float4 aR[4];
    uint4  bhR[2], blR[2];

    {
        const float* ap = A + (size_t)(m0 + lrow) * K + lko;
#pragma unroll
        for (int i = 0; i < 4; i++) aR[i] = ((const float4*)ap)[i];
        const __nv_bfloat16* bp = Bth + (size_t)(n0 + lrow) * K + lko;
        const __nv_bfloat16* lp = Btl + (size_t)(n0 + lrow) * K + lko;
        bhR[0] = ((const uint4*)bp)[0]; bhR[1] = ((const uint4*)bp)[1];
        blR[0] = ((const uint4*)lp)[0]; blR[1] = ((const uint4*)lp)[1];
    }

    for (int c = 0; c < nch; c++) {
        const int buf = c & 1;
        char* base = smem + buf * BUF_B;
        __syncthreads();
        {
            const int rb = lrow * (ASTRIDE * 2) + lko * 2;
#pragma unroll
            for (int i = 0; i < 2; i++) {
                float4 f0 = aR[i * 2], f1 = aR[i * 2 + 1];
                __nv_bfloat162 h01 = __floats2bfloat162_rn(f0.x, f0.y);
                __nv_bfloat162 h23 = __floats2bfloat162_rn(f0.z, f0.w);
                __nv_bfloat162 h45 = __floats2bfloat162_rn(f1.x, f1.y);
                __nv_bfloat162 h67 = __floats2bfloat162_rn(f1.z, f1.w);
                __nv_bfloat162 l01 = __floats2bfloat162_rn(f0.x - __bfloat162float(h01.x),
                                                           f0.y - __bfloat162float(h01.y));
                __nv_bfloat162 l23 = __floats2bfloat162_rn(f0.z - __bfloat162float(h23.x),
                                                           f0.w - __bfloat162float(h23.y));
                __nv_bfloat162 l45 = __floats2bfloat162_rn(f1.x - __bfloat162float(h45.x),
                                                           f1.y - __bfloat162float(h45.y));
                __nv_bfloat162 l67 = __floats2bfloat162_rn(f1.z - __bfloat162float(h67.x),
                                                           f1.w - __bfloat162float(h67.y));
                uint4 hv = { *(uint32_t*)&h01, *(uint32_t*)&h23,
                             *(uint32_t*)&h45, *(uint32_t*)&h67 };
                uint4 lv = { *(uint32_t*)&l01, *(uint32_t*)&l23,
                             *(uint32_t*)&l45, *(uint32_t*)&l67 };
                *(uint4*)(base + rb + i * 16)          = hv;
                *(uint4*)(base + TILE_B + rb + i * 16) = lv;
            }
            *(uint4*)(base + 2 * TILE_B + rb)      = bhR[0];
            *(uint4*)(base + 2 * TILE_B + rb + 16) = bhR[1];
            *(uint4*)(base + 3 * TILE_B + rb)      = blR[0];
            *(uint4*)(base + 3 * TILE_B + rb + 16) = blR[1];
        }
        __syncthreads();

        if (c + 1 < nch) {
            const int k0 = (c + 1) << 5;
            const float* ap = A + (size_t)(m0 + lrow) * K + k0 + lko;
#pragma unroll
            for (int i = 0; i < 4; i++) aR[i] = ((const float4*)ap)[i];
            const __nv_bfloat16* bp = Bth + (size_t)(n0 + lrow) * K + k0 + lko;
            const __nv_bfloat16* lp = Btl + (size_t)(n0 + lrow) * K + k0 + lko;
            bhR[0] = ((const uint4*)bp)[0]; bhR[1] = ((const uint4*)bp)[1];
            blR[0] = ((const uint4*)lp)[0]; blR[1] = ((const uint4*)lp)[1];
        }

        const uint32_t Ah = sbase + buf * BUF_B;
        const uint32_t Al = Ah + TILE_B;
        const uint32_t Bh = Ah + 2 * TILE_B;
        const uint32_t Bl = Ah + 3 * TILE_B;
#pragma unroll
        for (int ks = 0; ks < 2; ks++) {
            uint32_t ah[4][4], al[4][4], bh[4][2], blf[4][2];
#pragma unroll
            for (int mi = 0; mi < 4; mi++) {
                uint32_t off = ((warpM + mi * 16 + aRowOff) * ASTRIDE
                                + ks * 16 + aKpart) * 2;
                ldsm4(Ah + off, ah[mi]);
                ldsm4(Al + off, al[mi]);
            }
#pragma unroll
            for (int nj = 0; nj < 4; nj++) {
                uint32_t off = ((warpN + nj * 8 + bRowOff) * ASTRIDE
                                + ks * 16 + bKpart) * 2;
                ldsm2(Bh + off, bh[nj]);
                ldsm2(Bl + off, blf[nj]);
            }
#pragma unroll
            for (int mi = 0; mi < 4; mi++)
#pragma unroll
                for (int nj = 0; nj < 4; nj++) {
                    mma16816(acc[mi][nj], ah[mi], bh[nj]);
                    mma16816(acc[mi][nj], ah[mi], blf[nj]);
                    mma16816(acc[mi][nj], al[mi], bh[nj]);
                }
        }
    }

    // ---- epilogue ----
    const int g   = lane >> 2;
    const int tig = lane & 3;
#pragma unroll
    for (int mi = 0; mi < 4; mi++) {
#pragma unroll
        for (int half = 0; half < 2; half++) {
            int row = m0 + warpM + mi * 16 + g + half * 8;
#pragma unroll
            for (int nj = 0; nj < 4; nj++) {
                int col = n0 + warpN + nj * 8 + tig * 2;
                float vx = acc[mi][nj][half * 2 + 0];
                float vy = acc[mi][nj][half * 2 + 1];
                if (bias)  { vx += bias[col]; vy += bias[col + 1]; }
                if (mode == 2) {
                    // qkv split output: col -> (sect, head, d)
                    int sect = col >> 8;
                    int hh   = (col >> 6) & 3;
                    int d    = col & 63;
                    if (sect == 0) { vx *= 0.125f; vy *= 0.125f; }
                    size_t idx = (((size_t)(row >> 11) * 4 + hh) * SEQ
                                  + (row & (SEQ - 1))) * DEPTH + d;
                    __nv_bfloat162 hi = __floats2bfloat162_rn(vx, vy);
                    __nv_bfloat162 lo = __floats2bfloat162_rn(
                        vx - __bfloat162float(hi.x), vy - __bfloat162float(hi.y));
                    *(__nv_bfloat162*)(att + (size_t)(2 * sect) * ATT_R + idx)     = hi;
                    *(__nv_bfloat162*)(att + (size_t)(2 * sect + 1) * ATT_R + idx) = lo;
                } else {
                    if (resid) {
                        const float* rp = resid + (size_t)row * N + col;
                        vx += rp[0]; vy += rp[1];
                    }
                    if (mode == 1) {
                        vx = 0.5f * vx * (1.0f + erff(vx * 0.70710678118654752f));
                        vy = 0.5f * vy * (1.0f + erff(vy * 0.70710678118654752f));
                    }
                    *(float2*)(C + (size_t)row * N + col) = make_float2(vx, vy);
                }
            }
        }
    }
}

// ===================== flash attention via mma.sync =========================
// CTA: 64 queries of one (b,h); 4 warps, each m16. Key tiles of 64.
// Scores: 3-term split (QhKh + QhKl + QlKh); PV: 3-term (PhVh + PhVl + PlVh).
#define ATS 72                       // padded row stride (bf16 elems)
#define TBY (64 * ATS * 2)           // 9216 bytes per tile
#define QH_O 0
#define QL_O (1 * TBY)
#define KH_O (2 * TBY)
#define KL_O (3 * TBY)
#define VH_O (4 * TBY)
#define VL_O (5 * TBY)
#define ATT_SMEM (6 * TBY)           // 55296

__global__ void __launch_bounds__(128)
attn_mma(const __nv_bfloat16* __restrict__ att, float* __restrict__ ctx)
{
    extern __shared__ __align__(16) char sm[];
    const int tid  = threadIdx.x;
    const int wid  = tid >> 5;
    const int lane = tid & 31;
    const int bh   = blockIdx.y;
    const int q0   = blockIdx.x * 64;

    const size_t hb = (size_t)bh * SEQ * DEPTH;
    const __nv_bfloat16* qh = att + 0 * ATT_R + hb;
    const __nv_bfloat16* ql = att + 1 * ATT_R + hb;
    const __nv_bfloat16* kh = att + 2 * ATT_R + hb;
    const __nv_bfloat16* kl = att + 3 * ATT_R + hb;
    const __nv_bfloat16* vh = att + 4 * ATT_R + hb;
    const __nv_bfloat16* vl = att + 5 * ATT_R + hb;

    const int lrow = tid >> 1;
    const int ldh  = (tid & 1) * 32;

    // load Q tile once
    {
        const uint4* s0 = (const uint4*)(qh + (size_t)(q0 + lrow) * DEPTH + ldh);
        const uint4* s1 = (const uint4*)(ql + (size_t)(q0 + lrow) * DEPTH + ldh);
        uint4* d0 = (uint4*)(sm + QH_O + (lrow * ATS + ldh) * 2);
        uint4* d1 = (uint4*)(sm + QL_O + (lrow * ATS + ldh) * 2);
#pragma unroll
        for (int i = 0; i < 4; i++) { d0[i] = s0[i]; d1[i] = s1[i]; }
    }

    const uint32_t sb = smem_u32(sm);
    // ldmatrix lane-address components
    const int aRow = (lane & 7) + ((lane >> 3) & 1) * 8;   // A (Q, non-trans x4)
    const int aCol = ((lane >> 4) & 1) * 8;
    const int kRow = (lane & 7) + ((lane >> 4) & 1) * 8;   // B (K, non-trans x4)
    const int kCol = ((lane >> 3) & 1) * 8;
    const int vRow = (lane & 7) + ((lane >> 3) & 1) * 8;   // B (V, trans x4)
    const int vCol = ((lane >> 4) & 1) * 8;

    const uint32_t qh_a = sb + QH_O + ((wid * 16 + aRow) * ATS + aCol) * 2;
    const uint32_t ql_a = sb + QL_O + ((wid * 16 + aRow) * ATS + aCol) * 2;

    float o[8][4];
#pragma unroll
    for (int i = 0; i < 8; i++)
#pragma unroll
        for (int e = 0; e < 4; e++) o[i][e] = 0.f;
    float mrow0 = -1e30f, mrow1 = -1e30f, lrow0 = 0.f, lrow1 = 0.f;

    for (int kt = 0; kt < SEQ / 64; kt++) {
        __syncthreads();
        // ---- load K/V tile (hi+lo) ----
        {
            size_t go = (size_t)(kt * 64 + lrow) * DEPTH + ldh;
            int so = (lrow * ATS + ldh) * 2;
            const uint4* sk0 = (const uint4*)(kh + go);
            const uint4* sk1 = (const uint4*)(kl + go);
            const uint4* sv0 = (const uint4*)(vh + go);
            const uint4* sv1 = (const uint4*)(vl + go);
            uint4* dk0 = (uint4*)(sm + KH_O + so);
            uint4* dk1 = (uint4*)(sm + KL_O + so);
            uint4* dv0 = (uint4*)(sm + VH_O + so);
            uint4* dv1 = (uint4*)(sm + VL_O + so);
#pragma unroll
            for (int i = 0; i < 4; i++) {
                dk0[i] = sk0[i]; dk1[i] = sk1[i];
                dv0[i] = sv0[i]; dv1[i] = sv1[i];
            }
        }
        __syncthreads();

        // ---- scores S[16 x 64] ----
        float s[8][4];
#pragma unroll
        for (int i = 0; i < 8; i++)
#pragma unroll
            for (int e = 0; e < 4; e++) s[i][e] = 0.f;

#pragma unroll
        for (int kc = 0; kc < 4; kc++) {
            uint32_t a_h[4], a_l[4];
            ldsm4(qh_a + kc * 32, a_h);
            ldsm4(ql_a + kc * 32, a_l);
#pragma unroll
            for (int np = 0; np < 4; np++) {
                uint32_t b_h[4], b_l[4];
                uint32_t ka = sb + KH_O + ((np * 16 + kRow) * ATS + kc * 16 + kCol) * 2;
                ldsm4(ka, b_h);
                ldsm4(ka + (KL_O - KH_O), b_l);
                mma16816(s[2 * np],     a_h, b_h);
                mma16816(s[2 * np + 1], a_h, b_h + 2);
                mma16816(s[2 * np],     a_h, b_l);
                mma16816(s[2 * np + 1], a_h, b_l + 2);
                mma16816(s[2 * np],     a_l, b_h);
                mma16816(s[2 * np + 1], a_l, b_h + 2);
            }
        }

        // ---- online softmax ----
        float mx0 = -1e30f, mx1 = -1e30f;
#pragma unroll
        for (int i = 0; i < 8; i++) {
            mx0 = fmaxf(mx0, fmaxf(s[i][0], s[i][1]));
            mx1 = fmaxf(mx1, fmaxf(s[i][2], s[i][3]));
        }
        mx0 = fmaxf(mx0, __shfl_xor_sync(0xffffffff, mx0, 1));
        mx0 = fmaxf(mx0, __shfl_xor_sync(0xffffffff, mx0, 2));
        mx1 = fmaxf(mx1, __shfl_xor_sync(0xffffffff, mx1, 1));
        mx1 = fmaxf(mx1, __shfl_xor_sync(0xffffffff, mx1, 2));

        float mn0 = fmaxf(mrow0, mx0), mn1 = fmaxf(mrow1, mx1);
        float sc0 = __expf(mrow0 - mn0), sc1 = __expf(mrow1 - mn1);
        mrow0 = mn0; mrow1 = mn1;

        float ls0 = 0.f, ls1 = 0.f;
#pragma unroll
        for (int i = 0; i < 8; i++) {
            s[i][0] = __expf(s[i][0] - mn0); ls0 += s[i][0];
            s[i][1] = __expf(s[i][1] - mn0); ls0 += s[i][1];
            s[i][2] = __expf(s[i][2] - mn1); ls1 += s[i][2];
            s[i][3] = __expf(s[i][3] - mn1); ls1 += s[i][3];
        }
        ls0 += __shfl_xor_sync(0xffffffff, ls0, 1);
        ls0 += __shfl_xor_sync(0xffffffff, ls0, 2);
        ls1 += __shfl_xor_sync(0xffffffff, ls1, 1);
        ls1 += __shfl_xor_sync(0xffffffff, ls1, 2);
        lrow0 = lrow0 * sc0 + ls0;
        lrow1 = lrow1 * sc1 + ls1;

#pragma unroll
        for (int i = 0; i < 8; i++) {
            o[i][0] *= sc0; o[i][1] *= sc0;
            o[i][2] *= sc1; o[i][3] *= sc1;
        }

        // ---- PV: ctx += P @ V ----
#pragma unroll
        for (int kc = 0; kc < 4; kc++) {
            // repack P (C-frag of score ntiles 2kc,2kc+1 -> A-frag), split hi/lo
            uint32_t pa_h[4], pa_l[4];
#pragma unroll
            for (int half = 0; half < 2; half++) {
                float p0 = s[2 * kc + half][0], p1 = s[2 * kc + half][1];
                float p2 = s[2 * kc + half][2], p3 = s[2 * kc + half][3];
                __nv_bfloat162 h01 = __floats2bfloat162_rn(p0, p1);
                __nv_bfloat162 h23 = __floats2bfloat162_rn(p2, p3);
                __nv_bfloat162 l01 = __floats2bfloat162_rn(p0 - __bfloat162float(h01.x),
                                                           p1 - __bfloat162float(h01.y));
                __nv_bfloat162 l23 = __floats2bfloat162_rn(p2 - __bfloat162float(h23.x),
                                                           p3 - __bfloat162float(h23.y));
                pa_h[2 * half + 0] = *(uint32_t*)&h01;
                pa_h[2 * half + 1] = *(uint32_t*)&h23;
                pa_l[2 * half + 0] = *(uint32_t*)&l01;
                pa_l[2 * half + 1] = *(uint32_t*)&l23;
            }
            // wait: a-frag order is {a0,a1}=ntile 2kc (k0-15 low half? see text)
            // correct order: a0 = (row, k0..), a1 = (row+8, k0..), a2 = (row, k8..), a3 = (row+8, k8..)
            // ntile 2kc supplies k 0-7 -> a0 (c0,c1) and a1 (c2,c3); ntile 2kc+1 -> a2, a3.
            // pa as built: [0]=nt2kc c01, [1]=nt2kc c23, [2]=nt2kc+1 c01, [3]=nt2kc+1 c23
            // required:    a0 =nt2kc c01, a1 =nt2kc c23, a2 =nt2kc+1 c01, a3=nt2kc+1 c23  ✓
#pragma unroll
            for (int dp = 0; dp < 4; dp++) {
                uint32_t vb_h[4], vb_l[4];
                uint32_t va = sb + VH_O + ((kc * 16 + vRow) * ATS + dp * 16 + vCol) * 2;
                ldsm4t(va, vb_h);
                ldsm4t(va + (VL_O - VH_O), vb_l);
                mma16816(o[2 * dp],     pa_h, vb_h);
                mma16816(o[2 * dp + 1], pa_h, vb_h + 2);
                mma16816(o[2 * dp],     pa_h, vb_l);
                mma16816(o[2 * dp + 1], pa_h, vb_l + 2);
                mma16816(o[2 * dp],     pa_l, vb_h);
                mma16816(o[2 * dp + 1], pa_l, vb_h + 2);
            }
        }
    }

    // ---- write ctx ----
    const float inv0 = 1.f / lrow0;
    const float inv1 = 1.f / lrow1;
    const int b  = bh >> 2;
    const int hh = bh & 3;
    const int ra = q0 + wid * 16 + (lane >> 2);
    const int cb = hh * DEPTH + (lane & 3) * 2;
#pragma unroll
    for (int nt = 0; nt < 8; nt++) {
        int col = cb + nt * 8;
        *(float2*)(ctx + (size_t)(b * SEQ + ra) * DIM + col) =
            make_float2(o[nt][0] * inv0, o[nt][1] * inv0);
        *(float2*)(ctx + (size_t)(b * SEQ + ra + 8) * DIM + col) =
            make_float2(o[nt][2] * inv1, o[nt][3] * inv1);
    }
}

// ===================== launch ===============================================
extern "C" void kernel_launch(void* const* d_in, const int* in_sizes, int n_in,
                              void* d_out, int out_size)
{
    const float* x    = (const float*)d_in[0];
    const float* b1g  = (const float*)d_in[1];
    const float* b1b  = (const float*)d_in[2];
    const float* b1m  = (const float*)d_in[3];
    const float* b1v  = (const float*)d_in[4];
    const float* wq   = (const float*)d_in[5];
    const float* bq   = (const float*)d_in[6];
    const float* wk   = (const float*)d_in[7];
    const float* bk   = (const float*)d_in[8];
    const float* wv   = (const float*)d_in[9];
    const float* bv   = (const float*)d_in[10];
    const float* wo   = (const float*)d_in[11];
    const float* bo   = (const float*)d_in[12];
    const float* b2g  = (const float*)d_in[13];
    const float* b2b  = (const float*)d_in[14];
    const float* b2m  = (const float*)d_in[15];
    const float* b2v  = (const float*)d_in[16];
    const float* w1   = (const float*)d_in[17];
    const float* w2   = (const float*)d_in[18];
    float* out = (float*)d_out;

    float *p_bqkv, *p_b1f, *p_ctx, *p_x1, *p_m1;
    __nv_bfloat16 *p_att, *p_qkvTh, *p_qkvTl, *p_woTh, *p_woTl, *p_w1Th, *p_w1Tl, *p_w2Th, *p_w2Tl;
    cudaGetSymbolAddress((void**)&p_bqkv,  g_bqkv);
    cudaGetSymbolAddress((void**)&p_b1f,   g_b1f);
    cudaGetSymbolAddress((void**)&p_ctx,   g_ctx);
    cudaGetSymbolAddress((void**)&p_x1,    g_x1);
    cudaGetSymbolAddress((void**)&p_m1,    g_m1);
    cudaGetSymbolAddress((void**)&p_att,   g_att);
    cudaGetSymbolAddress((void**)&p_qkvTh, g_qkvT_hi);
    cudaGetSymbolAddress((void**)&p_qkvTl, g_qkvT_lo);
    cudaGetSymbolAddress((void**)&p_woTh,  g_woT_hi);
    cudaGetSymbolAddress((void**)&p_woTl,  g_woT_lo);
    cudaGetSymbolAddress((void**)&p_w1Th,  g_w1T_hi);
    cudaGetSymbolAddress((void**)&p_w1Tl,  g_w1T_lo);
    cudaGetSymbolAddress((void**)&p_w2Th,  g_w2T_hi);
    cudaGetSymbolAddress((void**)&p_w2Tl,  g_w2T_lo);

    cudaFuncSetAttribute(gemm_mma, cudaFuncAttributeMaxDynamicSharedMemorySize, GSMEM_B);
    cudaFuncSetAttribute(attn_mma, cudaFuncAttributeMaxDynamicSharedMemorySize, ATT_SMEM);

    // 1. fold BN, transpose, split weights
    prep_kernel<<<9, 256>>>(b1g, b1b, b1m, b1v, wq, bq, wk, bk, wv, bv,
                            b2g, b2b, b2m, b2v, w1, wo, w2);

    // 2. QKV projection, split-bf16 head-major output into g_att
    gemm_mma<<<dim3(6, 64), 256, GSMEM_B>>>(
        x, p_qkvTh, p_qkvTl, p_bqkv, nullptr, p_ctx, p_att,
        MROWS, 3 * DIM, DIM, 2);

    // 3. flash attention (tensor cores) -> g_ctx
    attn_mma<<<dim3(SEQ / 64, BATCH * HEADS), 128, ATT_SMEM>>>(p_att, p_ctx);

    // 4. out projection + residual: g_x1 = ctx @ wo + bo + x
    gemm_mma<<<dim3(2, 64), 256, GSMEM_B>>>(
        p_ctx, p_woTh, p_woTl, bo, x, p_x1, p_att, MROWS, DIM, DIM, 0);

    // 5. FFN1 (BN2 folded) + GELU
    gemm_mma<<<dim3(8, 64), 256, GSMEM_B>>>(
        p_x1, p_w1Th, p_w1Tl, p_b1f, nullptr, p_m1, p_att, MROWS, HID, DIM, 1);

    // 6. FFN2 + residual: out = m1 @ w2 + x1
    gemm_mma<<<dim3(2, 64), 256, GSMEM_B>>>(
        p_m1, p_w2Th, p_w2Tl, nullptr, p_x1, out, p_att, MROWS, DIM, HID, 0);
}

// round 6
// speedup vs baseline: 2.5922x; 1.2406x over previous
#include <cuda_runtime.h>
#include <cuda_bf16.h>
#include <math.h>
#include <stdint.h>

// Problem constants
#define BATCH 4
#define SEQ   2048
#define DIM   256
#define HEADS 4
#define DEPTH 64
#define HID   1024
#define MROWS (BATCH*SEQ)      // 8192
#define EPS   1e-3f

// ===================== PTX helpers ==========================================
__device__ __forceinline__ uint32_t smem_u32(const void* p) {
    uint32_t a;
    asm("{ .reg .u64 t; cvta.to.shared.u64 t, %1; cvt.u32.u64 %0, t; }"
        : "=r"(a) : "l"(p));
    return a;
}
__device__ __forceinline__ void ldsm4(uint32_t addr, uint32_t* r) {
    asm volatile("ldmatrix.sync.aligned.m8n8.x4.shared.b16 {%0,%1,%2,%3}, [%4];"
                 : "=r"(r[0]), "=r"(r[1]), "=r"(r[2]), "=r"(r[3]) : "r"(addr));
}
__device__ __forceinline__ void ldsm2(uint32_t addr, uint32_t* r) {
    asm volatile("ldmatrix.sync.aligned.m8n8.x2.shared.b16 {%0,%1}, [%2];"
                 : "=r"(r[0]), "=r"(r[1]) : "r"(addr));
}
__device__ __forceinline__ void mma16816(float* c, const uint32_t* a, const uint32_t* b) {
    asm volatile(
        "mma.sync.aligned.m16n8k16.row.col.f32.bf16.bf16.f32 "
        "{%0,%1,%2,%3}, {%4,%5,%6,%7}, {%8,%9}, {%0,%1,%2,%3};"
        : "+f"(c[0]), "+f"(c[1]), "+f"(c[2]), "+f"(c[3])
        : "r"(a[0]), "r"(a[1]), "r"(a[2]), "r"(a[3]), "r"(b[0]), "r"(b[1]));
}
__device__ __forceinline__ void mma1688(float* c, const uint32_t* a, const uint32_t* b) {
    asm volatile(
        "mma.sync.aligned.m16n8k8.row.col.f32.tf32.tf32.f32 "
        "{%0,%1,%2,%3}, {%4,%5,%6,%7}, {%8,%9}, {%0,%1,%2,%3};"
        : "+f"(c[0]), "+f"(c[1]), "+f"(c[2]), "+f"(c[3])
        : "r"(a[0]), "r"(a[1]), "r"(a[2]), "r"(a[3]), "r"(b[0]), "r"(b[1]));
}
__device__ __forceinline__ uint32_t f2tf(float x) {
    uint32_t r; asm("cvt.rna.tf32.f32 %0, %1;" : "=r"(r) : "f"(x)); return r;
}

// ===================== scratch (device globals) =============================
#define QR ((size_t)16 * SEQ * DEPTH)      // one attn region [BH=16][S][64]
__device__ float g_bqkv[3 * DIM];
__device__ float g_b1f[HID];
__device__ __align__(16) __nv_bfloat16 g_qkvT_hi[3 * DIM * DIM], g_qkvT_lo[3 * DIM * DIM];
__device__ __align__(16) __nv_bfloat16 g_woT_hi[DIM * DIM],      g_woT_lo[DIM * DIM];
__device__ __align__(16) __nv_bfloat16 g_w1T_hi[HID * DIM],      g_w1T_lo[HID * DIM];
__device__ __align__(16) __nv_bfloat16 g_w2T_hi[DIM * HID],      g_w2T_lo[DIM * HID];
__device__ __align__(16) float g_attf[3 * 16 * SEQ * DEPTH];   // q(scaled),k,v fp32(tf32)
__device__ float g_ctx[MROWS * DIM];
__device__ float g_x1[MROWS * DIM];
__device__ float g_m1[MROWS * HID];

__device__ __forceinline__ void split_bf16(float x, __nv_bfloat16& h, __nv_bfloat16& l) {
    h = __float2bfloat16_rn(x);
    l = __float2bfloat16_rn(x - __bfloat162float(h));
}

// ===================== prep: elementwise split/transpose ====================
#define N_QKV (3 * DIM * DIM)          // 196608
#define N_W1  (DIM * HID)              // 262144
#define N_WO  (DIM * DIM)              // 65536
#define N_W2  (HID * DIM)              // 262144
#define N_TOT (N_QKV + N_W1 + N_WO + N_W2)

__global__ void prep_split(
    const float* __restrict__ g1, const float* __restrict__ v1,
    const float* __restrict__ g2, const float* __restrict__ v2,
    const float* __restrict__ wq, const float* __restrict__ wk,
    const float* __restrict__ wv, const float* __restrict__ w1,
    const float* __restrict__ wo, const float* __restrict__ w2)
{
    int i = blockIdx.x * 256 + threadIdx.x;
    if (i < N_QKV) {
        int d = i / (3 * DIM), col = i % (3 * DIM);
        const float* w = (col < DIM) ? wq : (col < 2 * DIM) ? wk : wv;
        int c = col & (DIM - 1);
        float a = g1[d] * rsqrtf(v1[d] + EPS);
        float val = a * w[d * DIM + c];
        __nv_bfloat16 h, l; split_bf16(val, h, l);
        g_qkvT_hi[col * DIM + d] = h; g_qkvT_lo[col * DIM + d] = l;
    } else if (i < N_QKV + N_W1) {
        int j = i - N_QKV; int d = j / HID, c = j % HID;
        float a = g2[d] * rsqrtf(v2[d] + EPS);
        float val = a * w1[j];
        __nv_bfloat16 h, l; split_bf16(val, h, l);
        g_w1T_hi[c * DIM + d] = h; g_w1T_lo[c * DIM + d] = l;
    } else if (i < N_QKV + N_W1 + N_WO) {
        int j = i - N_QKV - N_W1; int d = j / DIM, c = j % DIM;
        __nv_bfloat16 h, l; split_bf16(wo[j], h, l);
        g_woT_hi[c * DIM + d] = h; g_woT_lo[c * DIM + d] = l;
    } else if (i < N_TOT) {
        int j = i - N_QKV - N_W1 - N_WO; int k = j / DIM, n = j % DIM;
        __nv_bfloat16 h, l; split_bf16(w2[j], h, l);
        g_w2T_hi[n * HID + k] = h; g_w2T_lo[n * HID + k] = l;
    }
}

__global__ void prep_bias(
    const float* __restrict__ g1, const float* __restrict__ b1,
    const float* __restrict__ m1, const float* __restrict__ v1,
    const float* __restrict__ g2, const float* __restrict__ b2,
    const float* __restrict__ m2, const float* __restrict__ v2,
    const float* __restrict__ wq, const float* __restrict__ wk,
    const float* __restrict__ wv,
    const float* __restrict__ bq, const float* __restrict__ bk,
    const float* __restrict__ bv, const float* __restrict__ w1)
{
    int blk = blockIdx.x, t = threadIdx.x;
    if (blk < 3) {
        const float* w  = blk == 0 ? wq : blk == 1 ? wk : wv;
        const float* bb = blk == 0 ? bq : blk == 1 ? bk : bv;
        float acc = bb[t];
        for (int d = 0; d < DIM; d++) {
            float a = g1[d] * rsqrtf(v1[d] + EPS);
            float c = b1[d] - m1[d] * a;
            acc += c * w[d * DIM + t];
        }
        g_bqkv[blk * DIM + t] = acc;
    } else {
        int cb = (blk - 3) * 256;
        float acc = 0.f;
        for (int d = 0; d < DIM; d++) {
            float a = g2[d] * rsqrtf(v2[d] + EPS);
            float c = b2[d] - m2[d] * a;
            acc += c * w1[d * HID + cb + t];
        }
        g_b1f[cb + t] = acc;
    }
}

// ===================== mma.sync split-bf16 GEMM =============================
// mode 0: C = A@B + bias (+resid). mode 1: + GELU. mode 2: head-major fp32
// (tf32-rounded) q/k/v into g_attf (q pre-scaled by 0.125).
#define ASTRIDE 40
#define TILE_B  (128 * ASTRIDE * 2)
#define BUF_B   (4 * TILE_B)
#define GSMEM_B (2 * BUF_B)

__global__ void __launch_bounds__(256)
gemm_mma(const float* __restrict__ A,
         const __nv_bfloat16* __restrict__ Bth, const __nv_bfloat16* __restrict__ Btl,
         const float* __restrict__ bias, const float* __restrict__ resid,
         float* __restrict__ C, float* __restrict__ attf,
         int M, int N, int K, int mode)
{
    extern __shared__ __align__(16) char smem[];
    const int tid  = threadIdx.x;
    const int wid  = tid >> 5;
    const int lane = tid & 31;
    const int m0 = blockIdx.y * 128;
    const int n0 = blockIdx.x * 128;
    const int warpM = (wid & 1) * 64;
    const int warpN = (wid >> 1) * 32;

    const int lrow = tid >> 1;
    const int lko  = (tid & 1) * 16;

    const int aRowOff = (lane & 7) + ((lane >> 3) & 1) * 8;
    const int aKpart  = ((lane >> 4) & 1) * 8;
    const int bl2     = lane & 15;
    const int bRowOff = bl2 & 7;
    const int bKpart  = (bl2 >> 3) * 8;

    const uint32_t sbase = smem_u32(smem);

    float acc[4][4][4];
#pragma unroll
    for (int i = 0; i < 4; i++)
#pragma unroll
        for (int j = 0; j < 4; j++)
#pragma unroll
            for (int e = 0; e < 4; e++) acc[i][j][e] = 0.f;

    const int nch = K >> 5;
    float4 aR[4];
    uint4  bhR[2], blR[2];

    {
        const float* ap = A + (size_t)(m0 + lrow) * K + lko;
#pragma unroll
        for (int i = 0; i < 4; i++) aR[i] = ((const float4*)ap)[i];
        const __nv_bfloat16* bp = Bth + (size_t)(n0 + lrow) * K + lko;
        const __nv_bfloat16* lp = Btl + (size_t)(n0 + lrow) * K + lko;
        bhR[0] = ((const uint4*)bp)[0]; bhR[1] = ((const uint4*)bp)[1];
        blR[0] = ((const uint4*)lp)[0]; blR[1] = ((const uint4*)lp)[1];
    }

    for (int c = 0; c < nch; c++) {
        const int buf = c & 1;
        char* base = smem + buf * BUF_B;
        __syncthreads();
        {
            const int rb = lrow * (ASTRIDE * 2) + lko * 2;
#pragma unroll
            for (int i = 0; i < 2; i++) {
                float4 f0 = aR[i * 2], f1 = aR[i * 2 + 1];
                __nv_bfloat162 h01 = __floats2bfloat162_rn(f0.x, f0.y);
                __nv_bfloat162 h23 = __floats2bfloat162_rn(f0.z, f0.w);
                __nv_bfloat162 h45 = __floats2bfloat162_rn(f1.x, f1.y);
                __nv_bfloat162 h67 = __floats2bfloat162_rn(f1.z, f1.w);
                __nv_bfloat162 l01 = __floats2bfloat162_rn(f0.x - __bfloat162float(h01.x),
                                                           f0.y - __bfloat162float(h01.y));
                __nv_bfloat162 l23 = __floats2bfloat162_rn(f0.z - __bfloat162float(h23.x),
                                                           f0.w - __bfloat162float(h23.y));
                __nv_bfloat162 l45 = __floats2bfloat162_rn(f1.x - __bfloat162float(h45.x),
                                                           f1.y - __bfloat162float(h45.y));
                __nv_bfloat162 l67 = __floats2bfloat162_rn(f1.z - __bfloat162float(h67.x),
                                                           f1.w - __bfloat162float(h67.y));
                uint4 hv = { *(uint32_t*)&h01, *(uint32_t*)&h23,
                             *(uint32_t*)&h45, *(uint32_t*)&h67 };
                uint4 lv = { *(uint32_t*)&l01, *(uint32_t*)&l23,
                             *(uint32_t*)&l45, *(uint32_t*)&l67 };
                *(uint4*)(base + rb + i * 16)          = hv;
                *(uint4*)(base + TILE_B + rb + i * 16) = lv;
            }
            *(uint4*)(base + 2 * TILE_B + rb)      = bhR[0];
            *(uint4*)(base + 2 * TILE_B + rb + 16) = bhR[1];
            *(uint4*)(base + 3 * TILE_B + rb)      = blR[0];
            *(uint4*)(base + 3 * TILE_B + rb + 16) = blR[1];
        }
        __syncthreads();

        if (c + 1 < nch) {
            const int k0 = (c + 1) << 5;
            const float* ap = A + (size_t)(m0 + lrow) * K + k0 + lko;
#pragma unroll
            for (int i = 0; i < 4; i++) aR[i] = ((const float4*)ap)[i];
            const __nv_bfloat16* bp = Bth + (size_t)(n0 + lrow) * K + k0 + lko;
            const __nv_bfloat16* lp = Btl + (size_t)(n0 + lrow) * K + k0 + lko;
            bhR[0] = ((const uint4*)bp)[0]; bhR[1] = ((const uint4*)bp)[1];
            blR[0] = ((const uint4*)lp)[0]; blR[1] = ((const uint4*)lp)[1];
        }

        const uint32_t Ah = sbase + buf * BUF_B;
        const uint32_t Al = Ah + TILE_B;
        const uint32_t Bh = Ah + 2 * TILE_B;
        const uint32_t Bl = Ah + 3 * TILE_B;
#pragma unroll
        for (int ks = 0; ks < 2; ks++) {
            uint32_t ah[4][4], al[4][4], bh[4][2], blf[4][2];
#pragma unroll
            for (int mi = 0; mi < 4; mi++) {
                uint32_t off = ((warpM + mi * 16 + aRowOff) * ASTRIDE
                                + ks * 16 + aKpart) * 2;
                ldsm4(Ah + off, ah[mi]);
                ldsm4(Al + off, al[mi]);
            }
#pragma unroll
            for (int nj = 0; nj < 4; nj++) {
                uint32_t off = ((warpN + nj * 8 + bRowOff) * ASTRIDE
                                + ks * 16 + bKpart) * 2;
                ldsm2(Bh + off, bh[nj]);
                ldsm2(Bl + off, blf[nj]);
            }
#pragma unroll
            for (int mi = 0; mi < 4; mi++)
#pragma unroll
                for (int nj = 0; nj < 4; nj++) {
                    mma16816(acc[mi][nj], ah[mi], bh[nj]);
                    mma16816(acc[mi][nj], ah[mi], blf[nj]);
                    mma16816(acc[mi][nj], al[mi], bh[nj]);
                }
        }
    }

    // ---- epilogue ----
    const int g   = lane >> 2;
    const int tig = lane & 3;
#pragma unroll
    for (int mi = 0; mi < 4; mi++) {
#pragma unroll
        for (int half = 0; half < 2; half++) {
            int row = m0 + warpM + mi * 16 + g + half * 8;
#pragma unroll
            for (int nj = 0; nj < 4; nj++) {
                int col = n0 + warpN + nj * 8 + tig * 2;
                float vx = acc[mi][nj][half * 2 + 0];
                float vy = acc[mi][nj][half * 2 + 1];
                if (bias)  { vx += bias[col]; vy += bias[col + 1]; }
                if (mode == 2) {
                    int sect = col >> 8;
                    int hh   = (col >> 6) & 3;
                    int d    = col & 63;
                    if (sect == 0) { vx *= 0.125f; vy *= 0.125f; }
                    vx = __uint_as_float(f2tf(vx));
                    vy = __uint_as_float(f2tf(vy));
                    size_t idx = (((size_t)(row >> 11) * 4 + hh) * SEQ
                                  + (row & (SEQ - 1))) * DEPTH + d;
                    *(float2*)(attf + (size_t)sect * QR + idx) = make_float2(vx, vy);
                } else {
                    if (resid) {
                        const float* rp = resid + (size_t)row * N + col;
                        vx += rp[0]; vy += rp[1];
                    }
                    if (mode == 1) {
                        vx = 0.5f * vx * (1.0f + erff(vx * 0.70710678118654752f));
                        vy = 0.5f * vy * (1.0f + erff(vy * 0.70710678118654752f));
                    }
                    *(float2*)(C + (size_t)row * N + col) = make_float2(vx, vy);
                }
            }
        }
    }
}

// ===================== flash attention, tf32 mma ============================
// CTA: 128 queries of one (b,h), 8 warps (16 rows each). Key tiles of 64.
// Q/K/V stored frag-major in smem so each fragment is one LDS.128/LDS.64.
#define ATT_SMEM ((8192 + 4096 + 4096) * 4)   // 64 KB

__global__ void __launch_bounds__(256)
attn_tf32(const float* __restrict__ attf, float* __restrict__ ctx)
{
    extern __shared__ __align__(16) float sm[];
    float* Qs = sm;                 // 8192 floats: [(w*8+kc)*32 + lane]*4 + reg
    float* Ks = sm + 8192;          // 4096: [(nt*8+kc)*32 + lane]*2 + reg
    float* Vs = sm + 8192 + 4096;   // 4096: [(nt*8+kc)*32 + lane]*2 + reg

    const int tid  = threadIdx.x;
    const int wid  = tid >> 5;
    const int lane = tid & 31;
    const int bh   = blockIdx.y;
    const int q0   = blockIdx.x * 128;

    const float* qp = attf + 0 * QR + (size_t)bh * SEQ * DEPTH;
    const float* kp = attf + 1 * QR + (size_t)bh * SEQ * DEPTH;
    const float* vp = attf + 2 * QR + (size_t)bh * SEQ * DEPTH;

    // ---- load Q tile (frag-major) ----
    {
        int row = tid >> 1, dbase = (tid & 1) * 32;
        int w = row >> 4, r8 = row & 7, hfr = (row >> 3) & 1;
        const float4* src = (const float4*)(qp + (size_t)(q0 + row) * DEPTH + dbase);
#pragma unroll
        for (int j = 0; j < 8; j++) {
            float4 v = src[j];
            int d0 = dbase + j * 4;
            int kc = d0 >> 3, ch = (d0 >> 2) & 1;
            float* dst = Qs + ((size_t)((w * 8 + kc) * 32 + r8 * 4)) * 4 + hfr + 2 * ch;
            dst[0] = v.x; dst[4] = v.y; dst[8] = v.z; dst[12] = v.w;
        }
    }

    float o[8][4];
#pragma unroll
    for (int i = 0; i < 8; i++)
#pragma unroll
        for (int e = 0; e < 4; e++) o[i][e] = 0.f;
    float mrow0 = -1e30f, mrow1 = -1e30f, lsum0 = 0.f, lsum1 = 0.f;

    const int krow = tid >> 2, kq = tid & 3;
    const int srcA = (lane & 28) | ((lane & 3) >> 1);
    const int srcB = srcA + 2;
    const bool oddl = lane & 1;

    for (int kt = 0; kt < SEQ / 64; kt++) {
        __syncthreads();
        // ---- load K/V tile (frag-major) ----
        {
            const float4* ks = (const float4*)(kp + (size_t)(kt * 64 + krow) * DEPTH);
            const float4* vs = (const float4*)(vp + (size_t)(kt * 64 + krow) * DEPTH);
            int knt = krow >> 3, knn = krow & 7;
            int vkc = krow >> 3, vcc = krow & 3, vhf = (krow >> 2) & 1;
#pragma unroll
            for (int j = 0; j < 4; j++) {
                int f4 = kq + j * 4;
                float4 kv = ks[f4];
                float4 vv = vs[f4];
                int d0 = f4 * 4;
                int kc = d0 >> 3, khf = (d0 >> 2) & 1;
                float* kd = Ks + ((knt * 8 + kc) * 32 + knn * 4) * 2 + khf;
                kd[0] = kv.x; kd[2] = kv.y; kd[4] = kv.z; kd[6] = kv.w;
                int vnt = d0 >> 3, nnb = d0 & 7;
                float* vd = Vs + ((vnt * 8 + vkc) * 32 + nnb * 4 + vcc) * 2 + vhf;
                vd[0] = vv.x; vd[8] = vv.y; vd[16] = vv.z; vd[24] = vv.w;
            }
        }
        __syncthreads();

        // ---- scores S[16 x 64] per warp ----
        float s[8][4];
#pragma unroll
        for (int i = 0; i < 8; i++)
#pragma unroll
            for (int e = 0; e < 4; e++) s[i][e] = 0.f;

#pragma unroll
        for (int kc = 0; kc < 8; kc++) {
            uint4 aq = *(const uint4*)(Qs + ((wid * 8 + kc) * 32 + lane) * 4);
            uint32_t a[4] = { aq.x, aq.y, aq.z, aq.w };
#pragma unroll
            for (int nt = 0; nt < 8; nt++) {
                uint2 bk = *(const uint2*)(Ks + ((nt * 8 + kc) * 32 + lane) * 2);
                uint32_t b[2] = { bk.x, bk.y };
                mma1688(s[nt], a, b);
            }
        }

        // ---- online softmax ----
        float mx0 = -1e30f, mx1 = -1e30f;
#pragma unroll
        for (int i = 0; i < 8; i++) {
            mx0 = fmaxf(mx0, fmaxf(s[i][0], s[i][1]));
            mx1 = fmaxf(mx1, fmaxf(s[i][2], s[i][3]));
        }
        mx0 = fmaxf(mx0, __shfl_xor_sync(0xffffffff, mx0, 1));
        mx0 = fmaxf(mx0, __shfl_xor_sync(0xffffffff, mx0, 2));
        mx1 = fmaxf(mx1, __shfl_xor_sync(0xffffffff, mx1, 1));
        mx1 = fmaxf(mx1, __shfl_xor_sync(0xffffffff, mx1, 2));

        float mn0 = fmaxf(mrow0, mx0), mn1 = fmaxf(mrow1, mx1);
        float sc0 = __expf(mrow0 - mn0), sc1 = __expf(mrow1 - mn1);
        mrow0 = mn0; mrow1 = mn1;

        float ls0 = 0.f, ls1 = 0.f;
#pragma unroll
        for (int i = 0; i < 8; i++) {
            s[i][0] = __expf(s[i][0] - mn0); ls0 += s[i][0];
            s[i][1] = __expf(s[i][1] - mn0); ls0 += s[i][1];
            s[i][2] = __expf(s[i][2] - mn1); ls1 += s[i][2];
            s[i][3] = __expf(s[i][3] - mn1); ls1 += s[i][3];
        }
        ls0 += __shfl_xor_sync(0xffffffff, ls0, 1);
        ls0 += __shfl_xor_sync(0xffffffff, ls0, 2);
        ls1 += __shfl_xor_sync(0xffffffff, ls1, 1);
        ls1 += __shfl_xor_sync(0xffffffff, ls1, 2);
        lsum0 = lsum0 * sc0 + ls0;
        lsum1 = lsum1 * sc1 + ls1;

#pragma unroll
        for (int i = 0; i < 8; i++) {
            o[i][0] *= sc0; o[i][1] *= sc0;
            o[i][2] *= sc1; o[i][3] *= sc1;
        }

        // ---- PV: o += P @ V (repack C-frag -> A-frag via shuffles) ----
#pragma unroll
        for (int kc = 0; kc < 8; kc++) {
            float v00 = __shfl_sync(0xffffffff, s[kc][0], srcA);
            float v01 = __shfl_sync(0xffffffff, s[kc][1], srcA);
            float v10 = __shfl_sync(0xffffffff, s[kc][2], srcA);
            float v11 = __shfl_sync(0xffffffff, s[kc][3], srcA);
            float v20 = __shfl_sync(0xffffffff, s[kc][0], srcB);
            float v21 = __shfl_sync(0xffffffff, s[kc][1], srcB);
            float v30 = __shfl_sync(0xffffffff, s[kc][2], srcB);
            float v31 = __shfl_sync(0xffffffff, s[kc][3], srcB);
            uint32_t pa[4];
            pa[0] = f2tf(oddl ? v01 : v00);
            pa[1] = f2tf(oddl ? v11 : v10);
            pa[2] = f2tf(oddl ? v21 : v20);
            pa[3] = f2tf(oddl ? v31 : v30);
#pragma unroll
            for (int nt = 0; nt < 8; nt++) {
                uint2 bv = *(const uint2*)(Vs + ((nt * 8 + kc) * 32 + lane) * 2);
                uint32_t b[2] = { bv.x, bv.y };
                mma1688(o[nt], pa, b);
            }
        }
    }

    // ---- write ctx ----
    const float inv0 = 1.f / lsum0;
    const float inv1 = 1.f / lsum1;
    const int b  = bh >> 2;
    const int hh = bh & 3;
    const int ra = q0 + wid * 16 + (lane >> 2);
    const int cb = hh * DEPTH + (lane & 3) * 2;
#pragma unroll
    for (int nt = 0; nt < 8; nt++) {
        int col = cb + nt * 8;
        *(float2*)(ctx + (size_t)(b * SEQ + ra) * DIM + col) =
            make_float2(o[nt][0] * inv0, o[nt][1] * inv0);
        *(float2*)(ctx + (size_t)(b * SEQ + ra + 8) * DIM + col) =
            make_float2(o[nt][2] * inv1, o[nt][3] * inv1);
    }
}

// ===================== launch ===============================================
extern "C" void kernel_launch(void* const* d_in, const int* in_sizes, int n_in,
                              void* d_out, int out_size)
{
    const float* x    = (const float*)d_in[0];
    const float* b1g  = (const float*)d_in[1];
    const float* b1b  = (const float*)d_in[2];
    const float* b1m  = (const float*)d_in[3];
    const float* b1v  = (const float*)d_in[4];
    const float* wq   = (const float*)d_in[5];
    const float* bq   = (const float*)d_in[6];
    const float* wk   = (const float*)d_in[7];
    const float* bk   = (const float*)d_in[8];
    const float* wv   = (const float*)d_in[9];
    const float* bv   = (const float*)d_in[10];
    const float* wo   = (const float*)d_in[11];
    const float* bo   = (const float*)d_in[12];
    const float* b2g  = (const float*)d_in[13];
    const float* b2b  = (const float*)d_in[14];
    const float* b2m  = (const float*)d_in[15];
    const float* b2v  = (const float*)d_in[16];
    const float* w1   = (const float*)d_in[17];
    const float* w2   = (const float*)d_in[18];
    float* out = (float*)d_out;

    float *p_bqkv, *p_b1f, *p_ctx, *p_x1, *p_m1, *p_attf;
    __nv_bfloat16 *p_qkvTh, *p_qkvTl, *p_woTh, *p_woTl, *p_w1Th, *p_w1Tl, *p_w2Th, *p_w2Tl;
    cudaGetSymbolAddress((void**)&p_bqkv,  g_bqkv);
    cudaGetSymbolAddress((void**)&p_b1f,   g_b1f);
    cudaGetSymbolAddress((void**)&p_ctx,   g_ctx);
    cudaGetSymbolAddress((void**)&p_x1,    g_x1);
    cudaGetSymbolAddress((void**)&p_m1,    g_m1);
    cudaGetSymbolAddress((void**)&p_attf,  g_attf);
    cudaGetSymbolAddress((void**)&p_qkvTh, g_qkvT_hi);
    cudaGetSymbolAddress((void**)&p_qkvTl, g_qkvT_lo);
    cudaGetSymbolAddress((void**)&p_woTh,  g_woT_hi);
    cudaGetSymbolAddress((void**)&p_woTl,  g_woT_lo);
    cudaGetSymbolAddress((void**)&p_w1Th,  g_w1T_hi);
    cudaGetSymbolAddress((void**)&p_w1Tl,  g_w1T_lo);
    cudaGetSymbolAddress((void**)&p_w2Th,  g_w2T_hi);
    cudaGetSymbolAddress((void**)&p_w2Tl,  g_w2T_lo);

    cudaFuncSetAttribute(gemm_mma, cudaFuncAttributeMaxDynamicSharedMemorySize, GSMEM_B);
    cudaFuncSetAttribute(attn_tf32, cudaFuncAttributeMaxDynamicSharedMemorySize, ATT_SMEM);

    // 1. prep: weight split/transpose (elementwise) + bias folds
    prep_split<<<(N_TOT + 255) / 256, 256>>>(b1g, b1v, b2g, b2v,
                                             wq, wk, wv, w1, wo, w2);
    prep_bias<<<7, 256>>>(b1g, b1b, b1m, b1v, b2g, b2b, b2m, b2v,
                          wq, wk, wv, bq, bk, bv, w1);

    // 2. QKV projection, head-major tf32 output into g_attf
    gemm_mma<<<dim3(6, 64), 256, GSMEM_B>>>(
        x, p_qkvTh, p_qkvTl, p_bqkv, nullptr, p_ctx, p_attf,
        MROWS, 3 * DIM, DIM, 2);

    // 3. flash attention (tf32 tensor cores) -> g_ctx
    attn_tf32<<<dim3(SEQ / 128, BATCH * HEADS), 256, ATT_SMEM>>>(p_attf, p_ctx);

    // 4. out projection + residual: g_x1 = ctx @ wo + bo + x
    gemm_mma<<<dim3(2, 64), 256, GSMEM_B>>>(
        p_ctx, p_woTh, p_woTl, bo, x, p_x1, p_attf, MROWS, DIM, DIM, 0);

    // 5. FFN1 (BN2 folded) + GELU
    gemm_mma<<<dim3(8, 64), 256, GSMEM_B>>>(
        p_x1, p_w1Th, p_w1Tl, p_b1f, nullptr, p_m1, p_attf, MROWS, HID, DIM, 1);

    // 6. FFN2 + residual: out = m1 @ w2 + x1
    gemm_mma<<<dim3(2, 64), 256, GSMEM_B>>>(
        p_m1, p_w2Th, p_w2Tl, nullptr, p_x1, out, p_attf, MROWS, DIM, HID, 0);
}

// round 7
// speedup vs baseline: 2.5995x; 1.0028x over previous
#include <cuda_runtime.h>
#include <cuda_bf16.h>
#include <math.h>
#include <stdint.h>

// Problem constants
#define BATCH 4
#define SEQ   2048
#define DIM   256
#define HEADS 4
#define DEPTH 64
#define HID   1024
#define MROWS (BATCH*SEQ)      // 8192
#define EPS   1e-3f

// ===================== PTX helpers ==========================================
__device__ __forceinline__ uint32_t smem_u32(const void* p) {
    uint32_t a;
    asm("{ .reg .u64 t; cvta.to.shared.u64 t, %1; cvt.u32.u64 %0, t; }"
        : "=r"(a) : "l"(p));
    return a;
}
__device__ __forceinline__ void ldsm4(uint32_t addr, uint32_t* r) {
    asm volatile("ldmatrix.sync.aligned.m8n8.x4.shared.b16 {%0,%1,%2,%3}, [%4];"
                 : "=r"(r[0]), "=r"(r[1]), "=r"(r[2]), "=r"(r[3]) : "r"(addr));
}
__device__ __forceinline__ void ldsm2(uint32_t addr, uint32_t* r) {
    asm volatile("ldmatrix.sync.aligned.m8n8.x2.shared.b16 {%0,%1}, [%2];"
                 : "=r"(r[0]), "=r"(r[1]) : "r"(addr));
}
__device__ __forceinline__ void mma16816(float* c, const uint32_t* a, const uint32_t* b) {
    asm volatile(
        "mma.sync.aligned.m16n8k16.row.col.f32.bf16.bf16.f32 "
        "{%0,%1,%2,%3}, {%4,%5,%6,%7}, {%8,%9}, {%0,%1,%2,%3};"
        : "+f"(c[0]), "+f"(c[1]), "+f"(c[2]), "+f"(c[3])
        : "r"(a[0]), "r"(a[1]), "r"(a[2]), "r"(a[3]), "r"(b[0]), "r"(b[1]));
}
__device__ __forceinline__ void mma1688(float* c, const uint32_t* a, const uint32_t* b) {
    asm volatile(
        "mma.sync.aligned.m16n8k8.row.col.f32.tf32.tf32.f32 "
        "{%0,%1,%2,%3}, {%4,%5,%6,%7}, {%8,%9}, {%0,%1,%2,%3};"
        : "+f"(c[0]), "+f"(c[1]), "+f"(c[2]), "+f"(c[3])
        : "r"(a[0]), "r"(a[1]), "r"(a[2]), "r"(a[3]), "r"(b[0]), "r"(b[1]));
}
__device__ __forceinline__ uint32_t f2tf(float x) {
    uint32_t r; asm("cvt.rna.tf32.f32 %0, %1;" : "=r"(r) : "f"(x)); return r;
}

// ===================== scratch (device globals) =============================
#define QR ((size_t)16 * SEQ * DEPTH)      // one attn region [BH=16][S][64]
__device__ float g_bqkv[3 * DIM];
__device__ float g_b1f[HID];
__device__ __align__(16) __nv_bfloat16 g_qkvT_hi[3 * DIM * DIM], g_qkvT_lo[3 * DIM * DIM];
__device__ __align__(16) __nv_bfloat16 g_woT_hi[DIM * DIM],      g_woT_lo[DIM * DIM];
__device__ __align__(16) __nv_bfloat16 g_w1T_hi[HID * DIM],      g_w1T_lo[HID * DIM];
__device__ __align__(16) __nv_bfloat16 g_w2T_hi[DIM * HID],      g_w2T_lo[DIM * HID];
__device__ __align__(16) float g_attf[3 * 16 * SEQ * DEPTH];   // q(scaled),k,v fp32(tf32)
__device__ float g_ctx[MROWS * DIM];
__device__ float g_x1[MROWS * DIM];
__device__ float g_m1[MROWS * HID];

__device__ __forceinline__ void split_bf16(float x, __nv_bfloat16& h, __nv_bfloat16& l) {
    h = __float2bfloat16_rn(x);
    l = __float2bfloat16_rn(x - __bfloat162float(h));
}

// ===================== prep: elementwise split/transpose ====================
#define N_QKV (3 * DIM * DIM)          // 196608
#define N_W1  (DIM * HID)              // 262144
#define N_WO  (DIM * DIM)              // 65536
#define N_W2  (HID * DIM)              // 262144
#define N_TOT (N_QKV + N_W1 + N_WO + N_W2)

__global__ void prep_split(
    const float* __restrict__ g1, const float* __restrict__ v1,
    const float* __restrict__ g2, const float* __restrict__ v2,
    const float* __restrict__ wq, const float* __restrict__ wk,
    const float* __restrict__ wv, const float* __restrict__ w1,
    const float* __restrict__ wo, const float* __restrict__ w2)
{
    int i = blockIdx.x * 256 + threadIdx.x;
    if (i < N_QKV) {
        int d = i / (3 * DIM), col = i % (3 * DIM);
        const float* w = (col < DIM) ? wq : (col < 2 * DIM) ? wk : wv;
        int c = col & (DIM - 1);
        float a = g1[d] * rsqrtf(v1[d] + EPS);
        float val = a * w[d * DIM + c];
        __nv_bfloat16 h, l; split_bf16(val, h, l);
        g_qkvT_hi[col * DIM + d] = h; g_qkvT_lo[col * DIM + d] = l;
    } else if (i < N_QKV + N_W1) {
        int j = i - N_QKV; int d = j / HID, c = j % HID;
        float a = g2[d] * rsqrtf(v2[d] + EPS);
        float val = a * w1[j];
        __nv_bfloat16 h, l; split_bf16(val, h, l);
        g_w1T_hi[c * DIM + d] = h; g_w1T_lo[c * DIM + d] = l;
    } else if (i < N_QKV + N_W1 + N_WO) {
        int j = i - N_QKV - N_W1; int d = j / DIM, c = j % DIM;
        __nv_bfloat16 h, l; split_bf16(wo[j], h, l);
        g_woT_hi[c * DIM + d] = h; g_woT_lo[c * DIM + d] = l;
    } else if (i < N_TOT) {
        int j = i - N_QKV - N_W1 - N_WO; int k = j / DIM, n = j % DIM;
        __nv_bfloat16 h, l; split_bf16(w2[j], h, l);
        g_w2T_hi[n * HID + k] = h; g_w2T_lo[n * HID + k] = l;
    }
}

__global__ void prep_bias(
    const float* __restrict__ g1, const float* __restrict__ b1,
    const float* __restrict__ m1, const float* __restrict__ v1,
    const float* __restrict__ g2, const float* __restrict__ b2,
    const float* __restrict__ m2, const float* __restrict__ v2,
    const float* __restrict__ wq, const float* __restrict__ wk,
    const float* __restrict__ wv,
    const float* __restrict__ bq, const float* __restrict__ bk,
    const float* __restrict__ bv, const float* __restrict__ w1)
{
    int blk = blockIdx.x, t = threadIdx.x;
    if (blk < 3) {
        const float* w  = blk == 0 ? wq : blk == 1 ? wk : wv;
        const float* bb = blk == 0 ? bq : blk == 1 ? bk : bv;
        float acc = bb[t];
        for (int d = 0; d < DIM; d++) {
            float a = g1[d] * rsqrtf(v1[d] + EPS);
            float c = b1[d] - m1[d] * a;
            acc += c * w[d * DIM + t];
        }
        g_bqkv[blk * DIM + t] = acc;
    } else {
        int cb = (blk - 3) * 256;
        float acc = 0.f;
        for (int d = 0; d < DIM; d++) {
            float a = g2[d] * rsqrtf(v2[d] + EPS);
            float c = b2[d] - m2[d] * a;
            acc += c * w1[d * HID + cb + t];
        }
        g_b1f[cb + t] = acc;
    }
}

// ===================== mma.sync split-bf16 GEMM =============================
// mode 0: C = A@B + bias (+resid). mode 1: + GELU. mode 2: head-major fp32
// (tf32-rounded) q/k/v into g_attf (q pre-scaled by 0.125).
#define ASTRIDE 40
#define TILE_B  (128 * ASTRIDE * 2)
#define BUF_B   (4 * TILE_B)
#define GSMEM_B (2 * BUF_B)

__global__ void __launch_bounds__(256)
gemm_mma(const float* __restrict__ A,
         const __nv_bfloat16* __restrict__ Bth, const __nv_bfloat16* __restrict__ Btl,
         const float* __restrict__ bias, const float* __restrict__ resid,
         float* __restrict__ C, float* __restrict__ attf,
         int M, int N, int K, int mode)
{
    extern __shared__ __align__(16) char smem[];
    const int tid  = threadIdx.x;
    const int wid  = tid >> 5;
    const int lane = tid & 31;
    const int m0 = blockIdx.y * 128;
    const int n0 = blockIdx.x * 128;
    const int warpM = (wid & 1) * 64;
    const int warpN = (wid >> 1) * 32;

    const int lrow = tid >> 1;
    const int lko  = (tid & 1) * 16;

    const int aRowOff = (lane & 7) + ((lane >> 3) & 1) * 8;
    const int aKpart  = ((lane >> 4) & 1) * 8;
    const int bl2     = lane & 15;
    const int bRowOff = bl2 & 7;
    const int bKpart  = (bl2 >> 3) * 8;

    const uint32_t sbase = smem_u32(smem);

    float acc[4][4][4];
#pragma unroll
    for (int i = 0; i < 4; i++)
#pragma unroll
        for (int j = 0; j < 4; j++)
#pragma unroll
            for (int e = 0; e < 4; e++) acc[i][j][e] = 0.f;

    const int nch = K >> 5;
    float4 aR[4];
    uint4  bhR[2], blR[2];

    {
        const float* ap = A + (size_t)(m0 + lrow) * K + lko;
#pragma unroll
        for (int i = 0; i < 4; i++) aR[i] = ((const float4*)ap)[i];
        const __nv_bfloat16* bp = Bth + (size_t)(n0 + lrow) * K + lko;
        const __nv_bfloat16* lp = Btl + (size_t)(n0 + lrow) * K + lko;
        bhR[0] = ((const uint4*)bp)[0]; bhR[1] = ((const uint4*)bp)[1];
        blR[0] = ((const uint4*)lp)[0]; blR[1] = ((const uint4*)lp)[1];
    }

    for (int c = 0; c < nch; c++) {
        const int buf = c & 1;
        char* base = smem + buf * BUF_B;
        __syncthreads();
        {
            const int rb = lrow * (ASTRIDE * 2) + lko * 2;
#pragma unroll
            for (int i = 0; i < 2; i++) {
                float4 f0 = aR[i * 2], f1 = aR[i * 2 + 1];
                __nv_bfloat162 h01 = __floats2bfloat162_rn(f0.x, f0.y);
                __nv_bfloat162 h23 = __floats2bfloat162_rn(f0.z, f0.w);
                __nv_bfloat162 h45 = __floats2bfloat162_rn(f1.x, f1.y);
                __nv_bfloat162 h67 = __floats2bfloat162_rn(f1.z, f1.w);
                __nv_bfloat162 l01 = __floats2bfloat162_rn(f0.x - __bfloat162float(h01.x),
                                                           f0.y - __bfloat162float(h01.y));
                __nv_bfloat162 l23 = __floats2bfloat162_rn(f0.z - __bfloat162float(h23.x),
                                                           f0.w - __bfloat162float(h23.y));
                __nv_bfloat162 l45 = __floats2bfloat162_rn(f1.x - __bfloat162float(h45.x),
                                                           f1.y - __bfloat162float(h45.y));
                __nv_bfloat162 l67 = __floats2bfloat162_rn(f1.z - __bfloat162float(h67.x),
                                                           f1.w - __bfloat162float(h67.y));
                uint4 hv = { *(uint32_t*)&h01, *(uint32_t*)&h23,
                             *(uint32_t*)&h45, *(uint32_t*)&h67 };
                uint4 lv = { *(uint32_t*)&l01, *(uint32_t*)&l23,
                             *(uint32_t*)&l45, *(uint32_t*)&l67 };
                *(uint4*)(base + rb + i * 16)          = hv;
                *(uint4*)(base + TILE_B + rb + i * 16) = lv;
            }
            *(uint4*)(base + 2 * TILE_B + rb)      = bhR[0];
            *(uint4*)(base + 2 * TILE_B + rb + 16) = bhR[1];
            *(uint4*)(base + 3 * TILE_B + rb)      = blR[0];
            *(uint4*)(base + 3 * TILE_B + rb + 16) = blR[1];
        }
        __syncthreads();

        if (c + 1 < nch) {
            const int k0 = (c + 1) << 5;
            const float* ap = A + (size_t)(m0 + lrow) * K + k0 + lko;
#pragma unroll
            for (int i = 0; i < 4; i++) aR[i] = ((const float4*)ap)[i];
            const __nv_bfloat16* bp = Bth + (size_t)(n0 + lrow) * K + k0 + lko;
            const __nv_bfloat16* lp = Btl + (size_t)(n0 + lrow) * K + k0 + lko;
            bhR[0] = ((const uint4*)bp)[0]; bhR[1] = ((const uint4*)bp)[1];
            blR[0] = ((const uint4*)lp)[0]; blR[1] = ((const uint4*)lp)[1];
        }

        const uint32_t Ah = sbase + buf * BUF_B;
        const uint32_t Al = Ah + TILE_B;
        const uint32_t Bh = Ah + 2 * TILE_B;
        const uint32_t Bl = Ah + 3 * TILE_B;
#pragma unroll
        for (int ks = 0; ks < 2; ks++) {
            uint32_t ah[4][4], al[4][4], bh[4][2], blf[4][2];
#pragma unroll
            for (int mi = 0; mi < 4; mi++) {
                uint32_t off = ((warpM + mi * 16 + aRowOff) * ASTRIDE
                                + ks * 16 + aKpart) * 2;
                ldsm4(Ah + off, ah[mi]);
                ldsm4(Al + off, al[mi]);
            }
#pragma unroll
            for (int nj = 0; nj < 4; nj++) {
                uint32_t off = ((warpN + nj * 8 + bRowOff) * ASTRIDE
                                + ks * 16 + bKpart) * 2;
                ldsm2(Bh + off, bh[nj]);
                ldsm2(Bl + off, blf[nj]);
            }
#pragma unroll
            for (int mi = 0; mi < 4; mi++)
#pragma unroll
                for (int nj = 0; nj < 4; nj++) {
                    mma16816(acc[mi][nj], ah[mi], bh[nj]);
                    mma16816(acc[mi][nj], ah[mi], blf[nj]);
                    mma16816(acc[mi][nj], al[mi], bh[nj]);
                }
        }
    }

    // ---- epilogue ----
    const int g   = lane >> 2;
    const int tig = lane & 3;
#pragma unroll
    for (int mi = 0; mi < 4; mi++) {
#pragma unroll
        for (int half = 0; half < 2; half++) {
            int row = m0 + warpM + mi * 16 + g + half * 8;
#pragma unroll
            for (int nj = 0; nj < 4; nj++) {
                int col = n0 + warpN + nj * 8 + tig * 2;
                float vx = acc[mi][nj][half * 2 + 0];
                float vy = acc[mi][nj][half * 2 + 1];
                if (bias)  { vx += bias[col]; vy += bias[col + 1]; }
                if (mode == 2) {
                    int sect = col >> 8;
                    int hh   = (col >> 6) & 3;
                    int d    = col & 63;
                    if (sect == 0) { vx *= 0.125f; vy *= 0.125f; }
                    vx = __uint_as_float(f2tf(vx));
                    vy = __uint_as_float(f2tf(vy));
                    size_t idx = (((size_t)(row >> 11) * 4 + hh) * SEQ
                                  + (row & (SEQ - 1))) * DEPTH + d;
                    *(float2*)(attf + (size_t)sect * QR + idx) = make_float2(vx, vy);
                } else {
                    if (resid) {
                        const float* rp = resid + (size_t)row * N + col;
                        vx += rp[0]; vy += rp[1];
                    }
                    if (mode == 1) {
                        vx = 0.5f * vx * (1.0f + erff(vx * 0.70710678118654752f));
                        vy = 0.5f * vy * (1.0f + erff(vy * 0.70710678118654752f));
                    }
                    *(float2*)(C + (size_t)row * N + col) = make_float2(vx, vy);
                }
            }
        }
    }
}

// ===================== flash attention, tf32 mma ============================
// CTA: 128 queries of one (b,h), 8 warps (16 rows each). Key tiles of 64.
// Q/K/V stored frag-major in smem so each fragment is one LDS.128/LDS.64.
#define ATT_SMEM ((8192 + 4096 + 4096) * 4)   // 64 KB

__global__ void __launch_bounds__(256)
attn_tf32(const float* __restrict__ attf, float* __restrict__ ctx)
{
    extern __shared__ __align__(16) float sm[];
    float* Qs = sm;                 // 8192 floats: [(w*8+kc)*32 + lane]*4 + reg
    float* Ks = sm + 8192;          // 4096: [(nt*8+kc)*32 + lane]*2 + reg
    float* Vs = sm + 8192 + 4096;   // 4096: [(nt*8+kc)*32 + lane]*2 + reg

    const int tid  = threadIdx.x;
    const int wid  = tid >> 5;
    const int lane = tid & 31;
    const int bh   = blockIdx.y;
    const int q0   = blockIdx.x * 128;

    const float* qp = attf + 0 * QR + (size_t)bh * SEQ * DEPTH;
    const float* kp = attf + 1 * QR + (size_t)bh * SEQ * DEPTH;
    const float* vp = attf + 2 * QR + (size_t)bh * SEQ * DEPTH;

    // ---- load Q tile (frag-major) ----
    {
        int row = tid >> 1, dbase = (tid & 1) * 32;
        int w = row >> 4, r8 = row & 7, hfr = (row >> 3) & 1;
        const float4* src = (const float4*)(qp + (size_t)(q0 + row) * DEPTH + dbase);
#pragma unroll
        for (int j = 0; j < 8; j++) {
            float4 v = src[j];
            int d0 = dbase + j * 4;
            int kc = d0 >> 3, ch = (d0 >> 2) & 1;
            float* dst = Qs + ((size_t)((w * 8 + kc) * 32 + r8 * 4)) * 4 + hfr + 2 * ch;
            dst[0] = v.x; dst[4] = v.y; dst[8] = v.z; dst[12] = v.w;
        }
    }

    float o[8][4];
#pragma unroll
    for (int i = 0; i < 8; i++)
#pragma unroll
        for (int e = 0; e < 4; e++) o[i][e] = 0.f;
    float mrow0 = -1e30f, mrow1 = -1e30f, lsum0 = 0.f, lsum1 = 0.f;

    const int krow = tid >> 2, kq = tid & 3;
    const int srcA = (lane & 28) | ((lane & 3) >> 1);
    const int srcB = srcA + 2;
    const bool oddl = lane & 1;

    for (int kt = 0; kt < SEQ / 64; kt++) {
        __syncthreads();
        // ---- load K/V tile (frag-major) ----
        {
            const float4* ks = (const float4*)(kp + (size_t)(kt * 64 + krow) * DEPTH);
            const float4* vs = (const float4*)(vp + (size_t)(kt * 64 + krow) * DEPTH);
            int knt = krow >> 3, knn = krow & 7;
            int vkc = krow >> 3, vcc = krow & 3, vhf = (krow >> 2) & 1;
#pragma unroll
            for (int j = 0; j < 4; j++) {
                int f4 = kq + j * 4;
                float4 kv = ks[f4];
                float4 vv = vs[f4];
                int d0 = f4 * 4;
                int kc = d0 >> 3, khf = (d0 >> 2) & 1;
                float* kd = Ks + ((knt * 8 + kc) * 32 + knn * 4) * 2 + khf;
                kd[0] = kv.x; kd[2] = kv.y; kd[4] = kv.z; kd[6] = kv.w;
                int vnt = d0 >> 3, nnb = d0 & 7;
                float* vd = Vs + ((vnt * 8 + vkc) * 32 + nnb * 4 + vcc) * 2 + vhf;
                vd[0] = vv.x; vd[8] = vv.y; vd[16] = vv.z; vd[24] = vv.w;
            }
        }
        __syncthreads();

        // ---- scores S[16 x 64] per warp ----
        float s[8][4];
#pragma unroll
        for (int i = 0; i < 8; i++)
#pragma unroll
            for (int e = 0; e < 4; e++) s[i][e] = 0.f;

#pragma unroll
        for (int kc = 0; kc < 8; kc++) {
            uint4 aq = *(const uint4*)(Qs + ((wid * 8 + kc) * 32 + lane) * 4);
            uint32_t a[4] = { aq.x, aq.y, aq.z, aq.w };
#pragma unroll
            for (int nt = 0; nt < 8; nt++) {
                uint2 bk = *(const uint2*)(Ks + ((nt * 8 + kc) * 32 + lane) * 2);
                uint32_t b[2] = { bk.x, bk.y };
                mma1688(s[nt], a, b);
            }
        }

        // ---- online softmax ----
        float mx0 = -1e30f, mx1 = -1e30f;
#pragma unroll
        for (int i = 0; i < 8; i++) {
            mx0 = fmaxf(mx0, fmaxf(s[i][0], s[i][1]));
            mx1 = fmaxf(mx1, fmaxf(s[i][2], s[i][3]));
        }
        mx0 = fmaxf(mx0, __shfl_xor_sync(0xffffffff, mx0, 1));
        mx0 = fmaxf(mx0, __shfl_xor_sync(0xffffffff, mx0, 2));
        mx1 = fmaxf(mx1, __shfl_xor_sync(0xffffffff, mx1, 1));
        mx1 = fmaxf(mx1, __shfl_xor_sync(0xffffffff, mx1, 2));

        float mn0 = fmaxf(mrow0, mx0), mn1 = fmaxf(mrow1, mx1);
        float sc0 = __expf(mrow0 - mn0), sc1 = __expf(mrow1 - mn1);
        mrow0 = mn0; mrow1 = mn1;

        float ls0 = 0.f, ls1 = 0.f;
#pragma unroll
        for (int i = 0; i < 8; i++) {
            s[i][0] = __expf(s[i][0] - mn0); ls0 += s[i][0];
            s[i][1] = __expf(s[i][1] - mn0); ls0 += s[i][1];
            s[i][2] = __expf(s[i][2] - mn1); ls1 += s[i][2];
            s[i][3] = __expf(s[i][3] - mn1); ls1 += s[i][3];
        }
        ls0 += __shfl_xor_sync(0xffffffff, ls0, 1);
        ls0 += __shfl_xor_sync(0xffffffff, ls0, 2);
        ls1 += __shfl_xor_sync(0xffffffff, ls1, 1);
        ls1 += __shfl_xor_sync(0xffffffff, ls1, 2);
        lsum0 = lsum0 * sc0 + ls0;
        lsum1 = lsum1 * sc1 + ls1;

#pragma unroll
        for (int i = 0; i < 8; i++) {
            o[i][0] *= sc0; o[i][1] *= sc0;
            o[i][2] *= sc1; o[i][3] *= sc1;
        }

        // ---- PV: o += P @ V (repack C-frag -> A-frag via shuffles) ----
#pragma unroll
        for (int kc = 0; kc < 8; kc++) {
            float v00 = __shfl_sync(0xffffffff, s[kc][0], srcA);
            float v01 = __shfl_sync(0xffffffff, s[kc][1], srcA);
            float v10 = __shfl_sync(0xffffffff, s[kc][2], srcA);
            float v11 = __shfl_sync(0xffffffff, s[kc][3], srcA);
            float v20 = __shfl_sync(0xffffffff, s[kc][0], srcB);
            float v21 = __shfl_sync(0xffffffff, s[kc][1], srcB);
            float v30 = __shfl_sync(0xffffffff, s[kc][2], srcB);
            float v31 = __shfl_sync(0xffffffff, s[kc][3], srcB);
            uint32_t pa[4];
            pa[0] = f2tf(oddl ? v01 : v00);
            pa[1] = f2tf(oddl ? v11 : v10);
            pa[2] = f2tf(oddl ? v21 : v20);
            pa[3] = f2tf(oddl ? v31 : v30);
#pragma unroll
            for (int nt = 0; nt < 8; nt++) {
                uint2 bv = *(const uint2*)(Vs + ((nt * 8 + kc) * 32 + lane) * 2);
                uint32_t b[2] = { bv.x, bv.y };
                mma1688(o[nt], pa, b);
            }
        }
    }

    // ---- write ctx ----
    const float inv0 = 1.f / lsum0;
    const float inv1 = 1.f / lsum1;
    const int b  = bh >> 2;
    const int hh = bh & 3;
    const int ra = q0 + wid * 16 + (lane >> 2);
    const int cb = hh * DEPTH + (lane & 3) * 2;
#pragma unroll
    for (int nt = 0; nt < 8; nt++) {
        int col = cb + nt * 8;
        *(float2*)(ctx + (size_t)(b * SEQ + ra) * DIM + col) =
            make_float2(o[nt][0] * inv0, o[nt][1] * inv0);
        *(float2*)(ctx + (size_t)(b * SEQ + ra + 8) * DIM + col) =
            make_float2(o[nt][2] * inv1, o[nt][3] * inv1);
    }
}

// ===================== launch ===============================================
extern "C" void kernel_launch(void* const* d_in, const int* in_sizes, int n_in,
                              void* d_out, int out_size)
{
    const float* x    = (const float*)d_in[0];
    const float* b1g  = (const float*)d_in[1];
    const float* b1b  = (const float*)d_in[2];
    const float* b1m  = (const float*)d_in[3];
    const float* b1v  = (const float*)d_in[4];
    const float* wq   = (const float*)d_in[5];
    const float* bq   = (const float*)d_in[6];
    const float* wk   = (const float*)d_in[7];
    const float* bk   = (const float*)d_in[8];
    const float* wv   = (const float*)d_in[9];
    const float* bv   = (const float*)d_in[10];
    const float* wo   = (const float*)d_in[11];
    const float* bo   = (const float*)d_in[12];
    const float* b2g  = (const float*)d_in[13];
    const float* b2b  = (const float*)d_in[14];
    const float* b2m  = (const float*)d_in[15];
    const float* b2v  = (const float*)d_in[16];
    const float* w1   = (const float*)d_in[17];
    const float* w2   = (const float*)d_in[18];
    float* out = (float*)d_out;

    float *p_bqkv, *p_b1f, *p_ctx, *p_x1, *p_m1, *p_attf;
    __nv_bfloat16 *p_qkvTh, *p_qkvTl, *p_woTh, *p_woTl, *p_w1Th, *p_w1Tl, *p_w2Th, *p_w2Tl;
    cudaGetSymbolAddress((void**)&p_bqkv,  g_bqkv);
    cudaGetSymbolAddress((void**)&p_b1f,   g_b1f);
    cudaGetSymbolAddress((void**)&p_ctx,   g_ctx);
    cudaGetSymbolAddress((void**)&p_x1,    g_x1);
    cudaGetSymbolAddress((void**)&p_m1,    g_m1);
    cudaGetSymbolAddress((void**)&p_attf,  g_attf);
    cudaGetSymbolAddress((void**)&p_qkvTh, g_qkvT_hi);
    cudaGetSymbolAddress((void**)&p_qkvTl, g_qkvT_lo);
    cudaGetSymbolAddress((void**)&p_woTh,  g_woT_hi);
    cudaGetSymbolAddress((void**)&p_woTl,  g_woT_lo);
    cudaGetSymbolAddress((void**)&p_w1Th,  g_w1T_hi);
    cudaGetSymbolAddress((void**)&p_w1Tl,  g_w1T_lo);
    cudaGetSymbolAddress((void**)&p_w2Th,  g_w2T_hi);
    cudaGetSymbolAddress((void**)&p_w2Tl,  g_w2T_lo);

    cudaFuncSetAttribute(gemm_mma, cudaFuncAttributeMaxDynamicSharedMemorySize, GSMEM_B);
    cudaFuncSetAttribute(attn_tf32, cudaFuncAttributeMaxDynamicSharedMemorySize, ATT_SMEM);

    // 1. prep: weight split/transpose (elementwise) + bias folds
    prep_split<<<(N_TOT + 255) / 256, 256>>>(b1g, b1v, b2g, b2v,
                                             wq, wk, wv, w1, wo, w2);
    prep_bias<<<7, 256>>>(b1g, b1b, b1m, b1v, b2g, b2b, b2m, b2v,
                          wq, wk, wv, bq, bk, bv, w1);

    // 2. QKV projection, head-major tf32 output into g_attf
    gemm_mma<<<dim3(6, 64), 256, GSMEM_B>>>(
        x, p_qkvTh, p_qkvTl, p_bqkv, nullptr, p_ctx, p_attf,
        MROWS, 3 * DIM, DIM, 2);

    // 3. flash attention (tf32 tensor cores) -> g_ctx
    attn_tf32<<<dim3(SEQ / 128, BATCH * HEADS), 256, ATT_SMEM>>>(p_attf, p_ctx);

    // 4. out projection + residual: g_x1 = ctx @ wo + bo + x
    gemm_mma<<<dim3(2, 64), 256, GSMEM_B>>>(
        p_ctx, p_woTh, p_woTl, bo, x, p_x1, p_attf, MROWS, DIM, DIM, 0);

    // 5. FFN1 (BN2 folded) + GELU
    gemm_mma<<<dim3(8, 64), 256, GSMEM_B>>>(
        p_x1, p_w1Th, p_w1Tl, p_b1f, nullptr, p_m1, p_attf, MROWS, HID, DIM, 1);

    // 6. FFN2 + residual: out = m1 @ w2 + x1
    gemm_mma<<<dim3(2, 64), 256, GSMEM_B>>>(
        p_m1, p_w2Th, p_w2Tl, nullptr, p_x1, out, p_attf, MROWS, DIM, HID, 0);
}

// round 8
// speedup vs baseline: 2.9316x; 1.1277x over previous
#include <cuda_runtime.h>
#include <cuda_bf16.h>
#include <math.h>
#include <stdint.h>

// Problem constants
#define BATCH 4
#define SEQ   2048
#define DIM   256
#define HEADS 4
#define DEPTH 64
#define HID   1024
#define MROWS (BATCH*SEQ)      // 8192
#define EPS   1e-3f
#define QSC   0.18033688011112042f   // 0.125 * log2(e)

// ===================== PTX helpers ==========================================
__device__ __forceinline__ uint32_t smem_u32(const void* p) {
    uint32_t a;
    asm("{ .reg .u64 t; cvta.to.shared.u64 t, %1; cvt.u32.u64 %0, t; }"
        : "=r"(a) : "l"(p));
    return a;
}
__device__ __forceinline__ void ldsm4(uint32_t addr, uint32_t* r) {
    asm volatile("ldmatrix.sync.aligned.m8n8.x4.shared.b16 {%0,%1,%2,%3}, [%4];"
                 : "=r"(r[0]), "=r"(r[1]), "=r"(r[2]), "=r"(r[3]) : "r"(addr));
}
__device__ __forceinline__ void ldsm2(uint32_t addr, uint32_t* r) {
    asm volatile("ldmatrix.sync.aligned.m8n8.x2.shared.b16 {%0,%1}, [%2];"
                 : "=r"(r[0]), "=r"(r[1]) : "r"(addr));
}
__device__ __forceinline__ void mma16816(float* c, const uint32_t* a, const uint32_t* b) {
    asm volatile(
        "mma.sync.aligned.m16n8k16.row.col.f32.bf16.bf16.f32 "
        "{%0,%1,%2,%3}, {%4,%5,%6,%7}, {%8,%9}, {%0,%1,%2,%3};"
        : "+f"(c[0]), "+f"(c[1]), "+f"(c[2]), "+f"(c[3])
        : "r"(a[0]), "r"(a[1]), "r"(a[2]), "r"(a[3]), "r"(b[0]), "r"(b[1]));
}
__device__ __forceinline__ void mma1688(float* c, const uint32_t* a, const uint32_t* b) {
    asm volatile(
        "mma.sync.aligned.m16n8k8.row.col.f32.tf32.tf32.f32 "
        "{%0,%1,%2,%3}, {%4,%5,%6,%7}, {%8,%9}, {%0,%1,%2,%3};"
        : "+f"(c[0]), "+f"(c[1]), "+f"(c[2]), "+f"(c[3])
        : "r"(a[0]), "r"(a[1]), "r"(a[2]), "r"(a[3]), "r"(b[0]), "r"(b[1]));
}
__device__ __forceinline__ uint32_t f2tf(float x) {
    uint32_t r; asm("cvt.rna.tf32.f32 %0, %1;" : "=r"(r) : "f"(x)); return r;
}
__device__ __forceinline__ float ex2f(float x) {
    float r; asm("ex2.approx.f32 %0, %1;" : "=f"(r) : "f"(x)); return r;
}

// ===================== scratch (device globals) =============================
#define QR ((size_t)16 * SEQ * DEPTH)      // one attn region (frag-major)
__device__ float g_bqkv[3 * DIM];
__device__ float g_b1f[HID];
__device__ __align__(16) __nv_bfloat16 g_qkvT_hi[3 * DIM * DIM], g_qkvT_lo[3 * DIM * DIM];
__device__ __align__(16) __nv_bfloat16 g_woT_hi[DIM * DIM],      g_woT_lo[DIM * DIM];
__device__ __align__(16) __nv_bfloat16 g_w1T_hi[HID * DIM],      g_w1T_lo[HID * DIM];
__device__ __align__(16) __nv_bfloat16 g_w2T_hi[DIM * HID],      g_w2T_lo[DIM * HID];
__device__ __align__(16) float g_attf[3 * 16 * SEQ * DEPTH];   // q,k,v frag-major
__device__ float g_ctx[MROWS * DIM];
__device__ float g_x1[MROWS * DIM];
__device__ float g_m1[MROWS * HID];

__device__ __forceinline__ void split_bf16(float x, __nv_bfloat16& h, __nv_bfloat16& l) {
    h = __float2bfloat16_rn(x);
    l = __float2bfloat16_rn(x - __bfloat162float(h));
}

// ===================== prep: elementwise split/transpose ====================
#define N_QKV (3 * DIM * DIM)          // 196608
#define N_W1  (DIM * HID)              // 262144
#define N_WO  (DIM * DIM)              // 65536
#define N_W2  (HID * DIM)              // 262144
#define N_TOT (N_QKV + N_W1 + N_WO + N_W2)

__global__ void prep_split(
    const float* __restrict__ g1, const float* __restrict__ v1,
    const float* __restrict__ g2, const float* __restrict__ v2,
    const float* __restrict__ wq, const float* __restrict__ wk,
    const float* __restrict__ wv, const float* __restrict__ w1,
    const float* __restrict__ wo, const float* __restrict__ w2)
{
    int i = blockIdx.x * 256 + threadIdx.x;
    if (i < N_QKV) {
        int d = i / (3 * DIM), col = i % (3 * DIM);
        const float* w = (col < DIM) ? wq : (col < 2 * DIM) ? wk : wv;
        int c = col & (DIM - 1);
        float a = g1[d] * rsqrtf(v1[d] + EPS);
        float val = a * w[d * DIM + c];
        __nv_bfloat16 h, l; split_bf16(val, h, l);
        g_qkvT_hi[col * DIM + d] = h; g_qkvT_lo[col * DIM + d] = l;
    } else if (i < N_QKV + N_W1) {
        int j = i - N_QKV; int d = j / HID, c = j % HID;
        float a = g2[d] * rsqrtf(v2[d] + EPS);
        float val = a * w1[j];
        __nv_bfloat16 h, l; split_bf16(val, h, l);
        g_w1T_hi[c * DIM + d] = h; g_w1T_lo[c * DIM + d] = l;
    } else if (i < N_QKV + N_W1 + N_WO) {
        int j = i - N_QKV - N_W1; int d = j / DIM, c = j % DIM;
        __nv_bfloat16 h, l; split_bf16(wo[j], h, l);
        g_woT_hi[c * DIM + d] = h; g_woT_lo[c * DIM + d] = l;
    } else if (i < N_TOT) {
        int j = i - N_QKV - N_W1 - N_WO; int k = j / DIM, n = j % DIM;
        __nv_bfloat16 h, l; split_bf16(w2[j], h, l);
        g_w2T_hi[n * HID + k] = h; g_w2T_lo[n * HID + k] = l;
    }
}

__global__ void prep_bias(
    const float* __restrict__ g1, const float* __restrict__ b1,
    const float* __restrict__ m1, const float* __restrict__ v1,
    const float* __restrict__ g2, const float* __restrict__ b2,
    const float* __restrict__ m2, const float* __restrict__ v2,
    const float* __restrict__ wq, const float* __restrict__ wk,
    const float* __restrict__ wv,
    const float* __restrict__ bq, const float* __restrict__ bk,
    const float* __restrict__ bv, const float* __restrict__ w1)
{
    int blk = blockIdx.x, t = threadIdx.x;
    if (blk < 3) {
        const float* w  = blk == 0 ? wq : blk == 1 ? wk : wv;
        const float* bb = blk == 0 ? bq : blk == 1 ? bk : bv;
        float acc = bb[t];
        for (int d = 0; d < DIM; d++) {
            float a = g1[d] * rsqrtf(v1[d] + EPS);
            float c = b1[d] - m1[d] * a;
            acc += c * w[d * DIM + t];
        }
        g_bqkv[blk * DIM + t] = acc;
    } else {
        int cb = (blk - 3) * 256;
        float acc = 0.f;
        for (int d = 0; d < DIM; d++) {
            float a = g2[d] * rsqrtf(v2[d] + EPS);
            float c = b2[d] - m2[d] * a;
            acc += c * w1[d * HID + cb + t];
        }
        g_b1f[cb + t] = acc;
    }
}

// ===================== mma.sync split-bf16 GEMM =============================
// mode 0: C = A@B + bias (+resid). mode 1: + GELU. mode 2: frag-major q/k/v
// (tf32-rounded, q pre-scaled by 0.125*log2e) into g_attf.
#define ASTRIDE 40
#define TILE_B  (128 * ASTRIDE * 2)
#define BUF_B   (4 * TILE_B)
#define GSMEM_B (2 * BUF_B)

__global__ void __launch_bounds__(256)
gemm_mma(const float* __restrict__ A,
         const __nv_bfloat16* __restrict__ Bth, const __nv_bfloat16* __restrict__ Btl,
         const float* __restrict__ bias, const float* __restrict__ resid,
         float* __restrict__ C, float* __restrict__ attf,
         int M, int N, int K, int mode)
{
    extern __shared__ __align__(16) char smem[];
    const int tid  = threadIdx.x;
    const int wid  = tid >> 5;
    const int lane = tid & 31;
    const int m0 = blockIdx.y * 128;
    const int n0 = blockIdx.x * 128;
    const int warpM = (wid & 1) * 64;
    const int warpN = (wid >> 1) * 32;

    const int lrow = tid >> 1;
    const int lko  = (tid & 1) * 16;

    const int aRowOff = (lane & 7) + ((lane >> 3) & 1) * 8;
    const int aKpart  = ((lane >> 4) & 1) * 8;
    const int bl2     = lane & 15;
    const int bRowOff = bl2 & 7;
    const int bKpart  = (bl2 >> 3) * 8;

    const uint32_t sbase = smem_u32(smem);

    float acc[4][4][4];
#pragma unroll
    for (int i = 0; i < 4; i++)
#pragma unroll
        for (int j = 0; j < 4; j++)
#pragma unroll
            for (int e = 0; e < 4; e++) acc[i][j][e] = 0.f;

    const int nch = K >> 5;
    float4 aR[4];
    uint4  bhR[2], blR[2];

    {
        const float* ap = A + (size_t)(m0 + lrow) * K + lko;
#pragma unroll
        for (int i = 0; i < 4; i++) aR[i] = ((const float4*)ap)[i];
        const __nv_bfloat16* bp = Bth + (size_t)(n0 + lrow) * K + lko;
        const __nv_bfloat16* lp = Btl + (size_t)(n0 + lrow) * K + lko;
        bhR[0] = ((const uint4*)bp)[0]; bhR[1] = ((const uint4*)bp)[1];
        blR[0] = ((const uint4*)lp)[0]; blR[1] = ((const uint4*)lp)[1];
    }

    for (int c = 0; c < nch; c++) {
        const int buf = c & 1;
        char* base = smem + buf * BUF_B;
        __syncthreads();
        {
            const int rb = lrow * (ASTRIDE * 2) + lko * 2;
#pragma unroll
            for (int i = 0; i < 2; i++) {
                float4 f0 = aR[i * 2], f1 = aR[i * 2 + 1];
                __nv_bfloat162 h01 = __floats2bfloat162_rn(f0.x, f0.y);
                __nv_bfloat162 h23 = __floats2bfloat162_rn(f0.z, f0.w);
                __nv_bfloat162 h45 = __floats2bfloat162_rn(f1.x, f1.y);
                __nv_bfloat162 h67 = __floats2bfloat162_rn(f1.z, f1.w);
                __nv_bfloat162 l01 = __floats2bfloat162_rn(f0.x - __bfloat162float(h01.x),
                                                           f0.y - __bfloat162float(h01.y));
                __nv_bfloat162 l23 = __floats2bfloat162_rn(f0.z - __bfloat162float(h23.x),
                                                           f0.w - __bfloat162float(h23.y));
                __nv_bfloat162 l45 = __floats2bfloat162_rn(f1.x - __bfloat162float(h45.x),
                                                           f1.y - __bfloat162float(h45.y));
                __nv_bfloat162 l67 = __floats2bfloat162_rn(f1.z - __bfloat162float(h67.x),
                                                           f1.w - __bfloat162float(h67.y));
                uint4 hv = { *(uint32_t*)&h01, *(uint32_t*)&h23,
                             *(uint32_t*)&h45, *(uint32_t*)&h67 };
                uint4 lv = { *(uint32_t*)&l01, *(uint32_t*)&l23,
                             *(uint32_t*)&l45, *(uint32_t*)&l67 };
                *(uint4*)(base + rb + i * 16)          = hv;
                *(uint4*)(base + TILE_B + rb + i * 16) = lv;
            }
            *(uint4*)(base + 2 * TILE_B + rb)      = bhR[0];
            *(uint4*)(base + 2 * TILE_B + rb + 16) = bhR[1];
            *(uint4*)(base + 3 * TILE_B + rb)      = blR[0];
            *(uint4*)(base + 3 * TILE_B + rb + 16) = blR[1];
        }
        __syncthreads();

        if (c + 1 < nch) {
            const int k0 = (c + 1) << 5;
            const float* ap = A + (size_t)(m0 + lrow) * K + k0 + lko;
#pragma unroll
            for (int i = 0; i < 4; i++) aR[i] = ((const float4*)ap)[i];
            const __nv_bfloat16* bp = Bth + (size_t)(n0 + lrow) * K + k0 + lko;
            const __nv_bfloat16* lp = Btl + (size_t)(n0 + lrow) * K + k0 + lko;
            bhR[0] = ((const uint4*)bp)[0]; bhR[1] = ((const uint4*)bp)[1];
            blR[0] = ((const uint4*)lp)[0]; blR[1] = ((const uint4*)lp)[1];
        }

        const uint32_t Ah = sbase + buf * BUF_B;
        const uint32_t Al = Ah + TILE_B;
        const uint32_t Bh = Ah + 2 * TILE_B;
        const uint32_t Bl = Ah + 3 * TILE_B;
#pragma unroll
        for (int ks = 0; ks < 2; ks++) {
            uint32_t ah[4][4], al[4][4], bh[4][2], blf[4][2];
#pragma unroll
            for (int mi = 0; mi < 4; mi++) {
                uint32_t off = ((warpM + mi * 16 + aRowOff) * ASTRIDE
                                + ks * 16 + aKpart) * 2;
                ldsm4(Ah + off, ah[mi]);
                ldsm4(Al + off, al[mi]);
            }
#pragma unroll
            for (int nj = 0; nj < 4; nj++) {
                uint32_t off = ((warpN + nj * 8 + bRowOff) * ASTRIDE
                                + ks * 16 + bKpart) * 2;
                ldsm2(Bh + off, bh[nj]);
                ldsm2(Bl + off, blf[nj]);
            }
#pragma unroll
            for (int mi = 0; mi < 4; mi++)
#pragma unroll
                for (int nj = 0; nj < 4; nj++) {
                    mma16816(acc[mi][nj], ah[mi], bh[nj]);
                    mma16816(acc[mi][nj], ah[mi], blf[nj]);
                    mma16816(acc[mi][nj], al[mi], bh[nj]);
                }
        }
    }

    // ---- epilogue ----
    const int g   = lane >> 2;
    const int tig = lane & 3;
#pragma unroll
    for (int mi = 0; mi < 4; mi++) {
#pragma unroll
        for (int half = 0; half < 2; half++) {
            int row = m0 + warpM + mi * 16 + g + half * 8;
#pragma unroll
            for (int nj = 0; nj < 4; nj++) {
                int col = n0 + warpN + nj * 8 + tig * 2;
                float vx = acc[mi][nj][half * 2 + 0];
                float vy = acc[mi][nj][half * 2 + 1];
                if (bias)  { vx += bias[col]; vy += bias[col + 1]; }
                if (mode == 2) {
                    // frag-major q/k/v output
                    int sect = col >> 8;
                    int hh   = (col >> 6) & 3;
                    int d    = col & 63;
                    int b    = row >> 11, sq = row & (SEQ - 1);
                    int bhx  = b * 4 + hh;
                    if (sect == 0) { vx *= QSC; vy *= QSC; }
                    vx = __uint_as_float(f2tf(vx));
                    vy = __uint_as_float(f2tf(vy));
                    size_t fx, fy;
                    if (sect == 0) {
                        int qt = sq >> 7, r = sq & 127;
                        int mtile = r >> 4, r8 = r & 7, hf = (r >> 3) & 1;
                        int kc = d >> 3, ch = (d >> 2) & 1;
                        size_t bse = ((size_t)bhx * 16 + qt) * 8192
                                   + (mtile * 8 + kc) * 128
                                   + (r8 * 4 + (d & 3)) * 4 + hf + 2 * ch;
                        fx = bse; fy = bse + 4;
                    } else if (sect == 1) {
                        int kt = sq >> 6, key = sq & 63;
                        int nt = key >> 3, kcp = d >> 4;
                        int krr = ((d >> 3) & 1) * 2 + ((d >> 2) & 1);
                        size_t bse = ((size_t)bhx * 32 + kt) * 4096
                                   + (nt * 4 + kcp) * 128
                                   + ((key & 7) * 4 + (d & 3)) * 4 + krr;
                        fx = bse; fy = bse + 4;
                    } else {
                        int kt = sq >> 6, key = sq & 63;
                        int nt = d >> 3, kcp = key >> 4;
                        int rr = ((key >> 3) & 1) * 2 + ((key >> 2) & 1);
                        size_t bse = ((size_t)bhx * 32 + kt) * 4096
                                   + (nt * 4 + kcp) * 128
                                   + ((d & 7) * 4 + (key & 3)) * 4 + rr;
                        fx = bse; fy = bse + 16;
                    }
                    float* reg = attf + (size_t)sect * QR;
                    reg[fx] = vx; reg[fy] = vy;
                } else {
                    if (resid) {
                        const float* rp = resid + (size_t)row * N + col;
                        vx += rp[0]; vy += rp[1];
                    }
                    if (mode == 1) {
                        vx = 0.5f * vx * (1.0f + erff(vx * 0.70710678118654752f));
                        vy = 0.5f * vy * (1.0f + erff(vy * 0.70710678118654752f));
                    }
                    *(float2*)(C + (size_t)row * N + col) = make_float2(vx, vy);
                }
            }
        }
    }
}

// ===================== flash attention, tf32 mma ============================
// CTA: 128 queries of one (b,h), 4 warps x 32 rows. Key tiles of 64.
// Q/K/V arrive in gmem frag-major; tile loads are straight uint4 copies.
#define ATP 132                          // padded tile stride (floats)
#define ATT_SMEM (128 * ATP * 4)         // 67584 bytes

__global__ void __launch_bounds__(128)
attn_tf32(const float* __restrict__ attf, float* __restrict__ ctx)
{
    extern __shared__ __align__(16) float sm[];
    float* Qs = sm;                  // 64 tiles
    float* Ks = sm + 64 * ATP;       // 32 tiles
    float* Vs = sm + 96 * ATP;       // 32 tiles

    const int tid  = threadIdx.x;
    const int wid  = tid >> 5;
    const int lane = tid & 31;
    const int bh   = blockIdx.y;
    const int q0   = blockIdx.x * 128;

    // ---- Q tile copy (once) ----
    {
        const uint4* qsrc = (const uint4*)(attf
            + ((size_t)bh * 16 + blockIdx.x) * 8192);
#pragma unroll
        for (int u = 0; u < 16; u++) {
            int g4 = tid + u * 128;
            *(uint4*)(Qs + (g4 >> 5) * ATP + (g4 & 31) * 4) = qsrc[g4];
        }
    }

    float o[2][8][4];
#pragma unroll
    for (int mt = 0; mt < 2; mt++)
#pragma unroll
        for (int nt = 0; nt < 8; nt++)
#pragma unroll
            for (int e = 0; e < 4; e++) o[mt][nt][e] = 0.f;
    float mrow[4] = { -1e30f, -1e30f, -1e30f, -1e30f };
    float lsum[4] = { 0.f, 0.f, 0.f, 0.f };

    const int srcA = (lane & 28) | ((lane & 3) >> 1);
    const int srcB = srcA + 2;
    const bool oddl = lane & 1;

    const uint4* kbase = (const uint4*)(attf + QR)     + (size_t)bh * 32 * 1024;
    const uint4* vbase = (const uint4*)(attf + 2 * QR) + (size_t)bh * 32 * 1024;

    for (int kt = 0; kt < SEQ / 64; kt++) {
        __syncthreads();
        {
            const uint4* ks = kbase + (size_t)kt * 1024;
            const uint4* vs = vbase + (size_t)kt * 1024;
#pragma unroll
            for (int u = 0; u < 8; u++) {
                int g4 = tid + u * 128;
                int off = (g4 >> 5) * ATP + (g4 & 31) * 4;
                *(uint4*)(Ks + off) = ks[g4];
                *(uint4*)(Vs + off) = vs[g4];
            }
        }
        __syncthreads();

        // ---- scores S[32 x 64] per warp ----
        float s[2][8][4];
#pragma unroll
        for (int mt = 0; mt < 2; mt++)
#pragma unroll
            for (int nt = 0; nt < 8; nt++)
#pragma unroll
                for (int e = 0; e < 4; e++) s[mt][nt][e] = 0.f;

#pragma unroll
        for (int kcp = 0; kcp < 4; kcp++) {
            uint4 aE0 = *(const uint4*)(Qs + ((wid * 2 + 0) * 8 + 2 * kcp) * ATP + lane * 4);
            uint4 aO0 = *(const uint4*)(Qs + ((wid * 2 + 0) * 8 + 2 * kcp + 1) * ATP + lane * 4);
            uint4 aE1 = *(const uint4*)(Qs + ((wid * 2 + 1) * 8 + 2 * kcp) * ATP + lane * 4);
            uint4 aO1 = *(const uint4*)(Qs + ((wid * 2 + 1) * 8 + 2 * kcp + 1) * ATP + lane * 4);
#pragma unroll
            for (int nt = 0; nt < 8; nt++) {
                uint4 kb = *(const uint4*)(Ks + (nt * 4 + kcp) * ATP + lane * 4);
                uint32_t bE[2] = { kb.x, kb.y }, bO[2] = { kb.z, kb.w };
                mma1688(s[0][nt], (const uint32_t*)&aE0, bE);
                mma1688(s[0][nt], (const uint32_t*)&aO0, bO);
                mma1688(s[1][nt], (const uint32_t*)&aE1, bE);
                mma1688(s[1][nt], (const uint32_t*)&aO1, bO);
            }
        }

        // ---- online softmax (log2 domain) ----
        float mx[4] = { -1e30f, -1e30f, -1e30f, -1e30f };
#pragma unroll
        for (int mt = 0; mt < 2; mt++)
#pragma unroll
            for (int nt = 0; nt < 8; nt++) {
                mx[2 * mt + 0] = fmaxf(mx[2 * mt + 0], fmaxf(s[mt][nt][0], s[mt][nt][1]));
                mx[2 * mt + 1] = fmaxf(mx[2 * mt + 1], fmaxf(s[mt][nt][2], s[mt][nt][3]));
            }
        float sc[4], ls[4] = { 0.f, 0.f, 0.f, 0.f };
#pragma unroll
        for (int i = 0; i < 4; i++) {
            mx[i] = fmaxf(mx[i], __shfl_xor_sync(0xffffffff, mx[i], 1));
            mx[i] = fmaxf(mx[i], __shfl_xor_sync(0xffffffff, mx[i], 2));
            float mn = fmaxf(mrow[i], mx[i]);
            sc[i] = ex2f(mrow[i] - mn);
            mrow[i] = mn;
        }
#pragma unroll
        for (int mt = 0; mt < 2; mt++)
#pragma unroll
            for (int nt = 0; nt < 8; nt++) {
                s[mt][nt][0] = ex2f(s[mt][nt][0] - mrow[2 * mt]);
                s[mt][nt][1] = ex2f(s[mt][nt][1] - mrow[2 * mt]);
                s[mt][nt][2] = ex2f(s[mt][nt][2] - mrow[2 * mt + 1]);
                s[mt][nt][3] = ex2f(s[mt][nt][3] - mrow[2 * mt + 1]);
                ls[2 * mt]     += s[mt][nt][0] + s[mt][nt][1];
                ls[2 * mt + 1] += s[mt][nt][2] + s[mt][nt][3];
            }
#pragma unroll
        for (int i = 0; i < 4; i++) {
            ls[i] += __shfl_xor_sync(0xffffffff, ls[i], 1);
            ls[i] += __shfl_xor_sync(0xffffffff, ls[i], 2);
            lsum[i] = lsum[i] * sc[i] + ls[i];
        }
#pragma unroll
        for (int mt = 0; mt < 2; mt++)
#pragma unroll
            for (int nt = 0; nt < 8; nt++) {
                o[mt][nt][0] *= sc[2 * mt];     o[mt][nt][1] *= sc[2 * mt];
                o[mt][nt][2] *= sc[2 * mt + 1]; o[mt][nt][3] *= sc[2 * mt + 1];
            }

        // ---- PV: o += P @ V ----
#pragma unroll
        for (int kcp = 0; kcp < 4; kcp++) {
            uint32_t pa[2][2][4];
#pragma unroll
            for (int kk = 0; kk < 2; kk++) {
                int kc = 2 * kcp + kk;
#pragma unroll
                for (int mt = 0; mt < 2; mt++) {
                    float v00 = __shfl_sync(0xffffffff, s[mt][kc][0], srcA);
                    float v01 = __shfl_sync(0xffffffff, s[mt][kc][1], srcA);
                    float v10 = __shfl_sync(0xffffffff, s[mt][kc][2], srcA);
                    float v11 = __shfl_sync(0xffffffff, s[mt][kc][3], srcA);
                    float v20 = __shfl_sync(0xffffffff, s[mt][kc][0], srcB);
                    float v21 = __shfl_sync(0xffffffff, s[mt][kc][1], srcB);
                    float v30 = __shfl_sync(0xffffffff, s[mt][kc][2], srcB);
                    float v31 = __shfl_sync(0xffffffff, s[mt][kc][3], srcB);
                    pa[kk][mt][0] = f2tf(oddl ? v01 : v00);
                    pa[kk][mt][1] = f2tf(oddl ? v11 : v10);
                    pa[kk][mt][2] = f2tf(oddl ? v21 : v20);
                    pa[kk][mt][3] = f2tf(oddl ? v31 : v30);
                }
            }
#pragma unroll
            for (int nt = 0; nt < 8; nt++) {
                uint4 vb = *(const uint4*)(Vs + (nt * 4 + kcp) * ATP + lane * 4);
                uint32_t bE[2] = { vb.x, vb.y }, bO[2] = { vb.z, vb.w };
                mma1688(o[0][nt], pa[0][0], bE);
                mma1688(o[0][nt], pa[1][0], bO);
                mma1688(o[1][nt], pa[0][1], bE);
                mma1688(o[1][nt], pa[1][1], bO);
            }
        }
    }

    // ---- write ctx ----
    float inv[4];
#pragma unroll
    for (int i = 0; i < 4; i++) inv[i] = 1.f / lsum[i];
    const int b  = bh >> 2;
    const int hh = bh & 3;
    const int g  = lane >> 2;
    const int tg = (lane & 3) * 2;
#pragma unroll
    for (int mt = 0; mt < 2; mt++) {
        int ra = q0 + wid * 32 + mt * 16 + g;
#pragma unroll
        for (int nt = 0; nt < 8; nt++) {
            int col = hh * DEPTH + tg + nt * 8;
            *(float2*)(ctx + (size_t)(b * SEQ + ra) * DIM + col) =
                make_float2(o[mt][nt][0] * inv[2 * mt], o[mt][nt][1] * inv[2 * mt]);
            *(float2*)(ctx + (size_t)(b * SEQ + ra + 8) * DIM + col) =
                make_float2(o[mt][nt][2] * inv[2 * mt + 1], o[mt][nt][3] * inv[2 * mt + 1]);
        }
    }
}

// ===================== launch ===============================================
extern "C" void kernel_launch(void* const* d_in, const int* in_sizes, int n_in,
                              void* d_out, int out_size)
{
    const float* x    = (const float*)d_in[0];
    const float* b1g  = (const float*)d_in[1];
    const float* b1b  = (const float*)d_in[2];
    const float* b1m  = (const float*)d_in[3];
    const float* b1v  = (const float*)d_in[4];
    const float* wq   = (const float*)d_in[5];
    const float* bq   = (const float*)d_in[6];
    const float* wk   = (const float*)d_in[7];
    const float* bk   = (const float*)d_in[8];
    const float* wv   = (const float*)d_in[9];
    const float* bv   = (const float*)d_in[10];
    const float* wo   = (const float*)d_in[11];
    const float* bo   = (const float*)d_in[12];
    const float* b2g  = (const float*)d_in[13];
    const float* b2b  = (const float*)d_in[14];
    const float* b2m  = (const float*)d_in[15];
    const float* b2v  = (const float*)d_in[16];
    const float* w1   = (const float*)d_in[17];
    const float* w2   = (const float*)d_in[18];
    float* out = (float*)d_out;

    float *p_bqkv, *p_b1f, *p_ctx, *p_x1, *p_m1, *p_attf;
    __nv_bfloat16 *p_qkvTh, *p_qkvTl, *p_woTh, *p_woTl, *p_w1Th, *p_w1Tl, *p_w2Th, *p_w2Tl;
    cudaGetSymbolAddress((void**)&p_bqkv,  g_bqkv);
    cudaGetSymbolAddress((void**)&p_b1f,   g_b1f);
    cudaGetSymbolAddress((void**)&p_ctx,   g_ctx);
    cudaGetSymbolAddress((void**)&p_x1,    g_x1);
    cudaGetSymbolAddress((void**)&p_m1,    g_m1);
    cudaGetSymbolAddress((void**)&p_attf,  g_attf);
    cudaGetSymbolAddress((void**)&p_qkvTh, g_qkvT_hi);
    cudaGetSymbolAddress((void**)&p_qkvTl, g_qkvT_lo);
    cudaGetSymbolAddress((void**)&p_woTh,  g_woT_hi);
    cudaGetSymbolAddress((void**)&p_woTl,  g_woT_lo);
    cudaGetSymbolAddress((void**)&p_w1Th,  g_w1T_hi);
    cudaGetSymbolAddress((void**)&p_w1Tl,  g_w1T_lo);
    cudaGetSymbolAddress((void**)&p_w2Th,  g_w2T_hi);
    cudaGetSymbolAddress((void**)&p_w2Tl,  g_w2T_lo);

    cudaFuncSetAttribute(gemm_mma, cudaFuncAttributeMaxDynamicSharedMemorySize, GSMEM_B);
    cudaFuncSetAttribute(attn_tf32, cudaFuncAttributeMaxDynamicSharedMemorySize, ATT_SMEM);

    // 1. prep: weight split/transpose (elementwise) + bias folds
    prep_split<<<(N_TOT + 255) / 256, 256>>>(b1g, b1v, b2g, b2v,
                                             wq, wk, wv, w1, wo, w2);
    prep_bias<<<7, 256>>>(b1g, b1b, b1m, b1v, b2g, b2b, b2m, b2v,
                          wq, wk, wv, bq, bk, bv, w1);

    // 2. QKV projection, frag-major tf32 output into g_attf
    gemm_mma<<<dim3(6, 64), 256, GSMEM_B>>>(
        x, p_qkvTh, p_qkvTl, p_bqkv, nullptr, p_ctx, p_attf,
        MROWS, 3 * DIM, DIM, 2);

    // 3. flash attention (tf32 tensor cores) -> g_ctx
    attn_tf32<<<dim3(SEQ / 128, BATCH * HEADS), 128, ATT_SMEM>>>(p_attf, p_ctx);

    // 4. out projection + residual: g_x1 = ctx @ wo + bo + x
    gemm_mma<<<dim3(2, 64), 256, GSMEM_B>>>(
        p_ctx, p_woTh, p_woTl, bo, x, p_x1, p_attf, MROWS, DIM, DIM, 0);

    // 5. FFN1 (BN2 folded) + GELU
    gemm_mma<<<dim3(8, 64), 256, GSMEM_B>>>(
        p_x1, p_w1Th, p_w1Tl, p_b1f, nullptr, p_m1, p_attf, MROWS, HID, DIM, 1);

    // 6. FFN2 + residual: out = m1 @ w2 + x1
    gemm_mma<<<dim3(2, 64), 256, GSMEM_B>>>(
        p_m1, p_w2Th, p_w2Tl, nullptr, p_x1, out, p_attf, MROWS, DIM, HID, 0);
}